// round 1
// baseline (speedup 1.0000x reference)
#include <cuda_runtime.h>
#include <math.h>

#define BATCH 8
#define CIN 1024
#define CI 512
#define HW 4096     // 64*64
#define HWP 1024    // 32*32

// ---- scratch (static device globals; no allocation at runtime) ----
__device__ float d_xp[(size_t)BATCH * CIN * HWP];     //  33.5 MB
__device__ float d_theta[(size_t)BATCH * CI * HW];    //  67 MB
__device__ float d_phi[(size_t)BATCH * CI * HWP];     //  16.8 MB
__device__ float d_g[(size_t)BATCH * CI * HWP];       //  16.8 MB
__device__ float d_attn[(size_t)BATCH * HW * HWP];    // 134 MB
__device__ float d_y[(size_t)BATCH * CI * HW];        //  67 MB
__device__ float d_z[(size_t)BATCH * CIN * HW];       // 134 MB
__device__ float d_mean[CIN];
__device__ float d_rstd[CIN];

// ---------------- maxpool 2x2 stride 2 ----------------
__global__ void maxpool_kernel(const float* __restrict__ x) {
    int idx = blockIdx.x * blockDim.x + threadIdx.x;
    if (idx >= BATCH * CIN * HWP) return;
    int j = idx & 31;
    int i = (idx >> 5) & 31;
    int bc = idx >> 10;
    const float* p = x + (size_t)bc * HW + (size_t)(i * 2) * 64 + j * 2;
    float m = fmaxf(fmaxf(p[0], p[1]), fmaxf(p[64], p[65]));
    d_xp[idx] = m;
}

// ---------------- tiled SGEMM ----------------
// C[m][n] = alpha * sum_k A(m,k) * B(k,n) + bias[m]
// AMODE 0: A stored [M][K] (k contiguous)    AMODE 1: A stored [K][M] (m contiguous)
// BMODE 0: B stored [K][N] (n contiguous)    BMODE 1: B stored [N][K] (k contiguous)
// Requires M%128==0, N%128==0, K%16==0 (true for all calls here).
#define BM 128
#define BN 128
#define BKK 16
#define TM 8
#define TN 8

template <int AMODE, int BMODE>
__global__ void __launch_bounds__(256) gemm_kernel(
    const float* __restrict__ A, const float* __restrict__ Bp,
    float* __restrict__ C, const float* __restrict__ bias,
    int M, int N, int K, size_t sA, size_t sB, size_t sC, float alpha)
{
    __shared__ float As[BKK][BM + 4];
    __shared__ float Bs[BKK][BN + 4];

    int b = blockIdx.z;
    A  += (size_t)b * sA;
    Bp += (size_t)b * sB;
    C  += (size_t)b * sC;

    const int m0 = blockIdx.y * BM;
    const int n0 = blockIdx.x * BN;
    const int tid = threadIdx.x;
    const int tx = tid & 15;
    const int ty = tid >> 4;

    float acc[TM][TN];
#pragma unroll
    for (int i = 0; i < TM; i++)
#pragma unroll
        for (int j = 0; j < TN; j++) acc[i][j] = 0.f;

    for (int k0 = 0; k0 < K; k0 += BKK) {
        // load A tile into As[k][m]
        if (AMODE == 0) {
#pragma unroll
            for (int i = 0; i < (BM * BKK) / 256; i++) {
                int l = tid + i * 256;
                int m = l / BKK, k = l % BKK;
                As[k][m] = A[(size_t)(m0 + m) * K + (k0 + k)];
            }
        } else {
#pragma unroll
            for (int i = 0; i < (BM * BKK) / 256; i++) {
                int l = tid + i * 256;
                int k = l / BM, m = l % BM;
                As[k][m] = A[(size_t)(k0 + k) * M + (m0 + m)];
            }
        }
        // load B tile into Bs[k][n]
        if (BMODE == 0) {
#pragma unroll
            for (int i = 0; i < (BN * BKK) / 256; i++) {
                int l = tid + i * 256;
                int k = l / BN, n = l % BN;
                Bs[k][n] = Bp[(size_t)(k0 + k) * N + (n0 + n)];
            }
        } else {
#pragma unroll
            for (int i = 0; i < (BN * BKK) / 256; i++) {
                int l = tid + i * 256;
                int n = l / BKK, k = l % BKK;
                Bs[k][n] = Bp[(size_t)(n0 + n) * K + (k0 + k)];
            }
        }
        __syncthreads();

#pragma unroll
        for (int k = 0; k < BKK; k++) {
            float ar[TM], br[TN];
#pragma unroll
            for (int i = 0; i < TM; i++) ar[i] = As[k][ty * TM + i];
#pragma unroll
            for (int j = 0; j < TN; j++) br[j] = Bs[k][tx * TN + j];
#pragma unroll
            for (int i = 0; i < TM; i++)
#pragma unroll
                for (int j = 0; j < TN; j++) acc[i][j] += ar[i] * br[j];
        }
        __syncthreads();
    }

#pragma unroll
    for (int i = 0; i < TM; i++) {
        int m = m0 + ty * TM + i;
        float bv = bias ? bias[m] : 0.f;
        float* crow = C + (size_t)m * N + n0 + tx * TN;
#pragma unroll
        for (int j = 0; j < TN; j++) crow[j] = acc[i][j] * alpha + bv;
    }
}

// ---------------- row softmax over d_attn (rows of length 1024) ----------------
__global__ void softmax_kernel() {
    size_t row = blockIdx.x;
    float* p = d_attn + row * HWP;
    int tid = threadIdx.x;  // 256 threads
    float v[4];
    float mx = -3.4e38f;
#pragma unroll
    for (int i = 0; i < 4; i++) { v[i] = p[tid + i * 256]; mx = fmaxf(mx, v[i]); }
#pragma unroll
    for (int o = 16; o > 0; o >>= 1) mx = fmaxf(mx, __shfl_xor_sync(0xffffffffu, mx, o));
    __shared__ float sm[8];
    __shared__ float sv[8];
    if ((tid & 31) == 0) sm[tid >> 5] = mx;
    __syncthreads();
    if (tid == 0) {
        float t = sm[0];
        for (int i = 1; i < 8; i++) t = fmaxf(t, sm[i]);
        sm[0] = t;
    }
    __syncthreads();
    mx = sm[0];
    float s = 0.f;
#pragma unroll
    for (int i = 0; i < 4; i++) { v[i] = __expf(v[i] - mx); s += v[i]; }
#pragma unroll
    for (int o = 16; o > 0; o >>= 1) s += __shfl_xor_sync(0xffffffffu, s, o);
    if ((tid & 31) == 0) sv[tid >> 5] = s;
    __syncthreads();
    if (tid == 0) {
        float t = 0.f;
        for (int i = 0; i < 8; i++) t += sv[i];
        sv[0] = t;
    }
    __syncthreads();
    float inv = 1.f / sv[0];
#pragma unroll
    for (int i = 0; i < 4; i++) p[tid + i * 256] = v[i] * inv;
}

// ---------------- BatchNorm batch statistics over d_z ----------------
__global__ void bn_stats_kernel() {
    int c = blockIdx.x;
    int tid = threadIdx.x;  // 256
    float s = 0.f, sq = 0.f;
    for (int b = 0; b < BATCH; b++) {
        const float* p = d_z + (size_t)(b * CIN + c) * HW;
        for (int n = tid; n < HW; n += 256) {
            float v = p[n];
            s += v;
            sq += v * v;
        }
    }
#pragma unroll
    for (int o = 16; o > 0; o >>= 1) {
        s += __shfl_xor_sync(0xffffffffu, s, o);
        sq += __shfl_xor_sync(0xffffffffu, sq, o);
    }
    __shared__ float ss[8], ssq[8];
    if ((tid & 31) == 0) { ss[tid >> 5] = s; ssq[tid >> 5] = sq; }
    __syncthreads();
    if (tid == 0) {
        float S = 0.f, SQ = 0.f;
        for (int i = 0; i < 8; i++) { S += ss[i]; SQ += ssq[i]; }
        const float inv_n = 1.0f / (float)(BATCH * HW);
        float mean = S * inv_n;
        float var = SQ * inv_n - mean * mean;
        d_mean[c] = mean;
        d_rstd[c] = rsqrtf(var + 1e-5f);
    }
}

// ---------------- final: out = x + gamma*(z-mean)*rstd + beta ----------------
__global__ void final_kernel(const float* __restrict__ x,
                             const float* __restrict__ gamma,
                             const float* __restrict__ beta,
                             float* __restrict__ out) {
    size_t idx = (size_t)blockIdx.x * blockDim.x + threadIdx.x;
    const size_t total = (size_t)BATCH * CIN * HW;
    if (idx >= total) return;
    int c = (int)((idx >> 12) & (CIN - 1));  // idx / 4096 % 1024
    out[idx] = x[idx] + (d_z[idx] - d_mean[c]) * d_rstd[c] * gamma[c] + beta[c];
}

extern "C" void kernel_launch(void* const* d_in, const int* in_sizes, int n_in,
                              void* d_out, int out_size) {
    const float* x       = (const float*)d_in[0];
    const float* theta_w = (const float*)d_in[1];
    const float* theta_b = (const float*)d_in[2];
    const float* phi_w   = (const float*)d_in[3];
    const float* phi_b   = (const float*)d_in[4];
    const float* g_w     = (const float*)d_in[5];
    const float* g_b     = (const float*)d_in[6];
    const float* wz_w    = (const float*)d_in[7];
    const float* wz_b    = (const float*)d_in[8];
    const float* gamma   = (const float*)d_in[9];
    const float* beta    = (const float*)d_in[10];
    float* out = (float*)d_out;

    float *xp, *theta, *phi, *g, *attn, *y, *z;
    cudaGetSymbolAddress((void**)&xp, d_xp);
    cudaGetSymbolAddress((void**)&theta, d_theta);
    cudaGetSymbolAddress((void**)&phi, d_phi);
    cudaGetSymbolAddress((void**)&g, d_g);
    cudaGetSymbolAddress((void**)&attn, d_attn);
    cudaGetSymbolAddress((void**)&y, d_y);
    cudaGetSymbolAddress((void**)&z, d_z);

    // 1. maxpool
    maxpool_kernel<<<(BATCH * CIN * HWP + 255) / 256, 256>>>(x);

    // 2. theta = theta_w @ x   [512 x 4096] per batch
    gemm_kernel<0, 0><<<dim3(HW / BN, CI / BM, BATCH), 256>>>(
        theta_w, x, theta, theta_b, CI, HW, CIN,
        0, (size_t)CIN * HW, (size_t)CI * HW, 1.0f);

    // 3. phi = phi_w @ xp   [512 x 1024] per batch
    gemm_kernel<0, 0><<<dim3(HWP / BN, CI / BM, BATCH), 256>>>(
        phi_w, xp, phi, phi_b, CI, HWP, CIN,
        0, (size_t)CIN * HWP, (size_t)CI * HWP, 1.0f);

    // 4. g = g_w @ xp
    gemm_kernel<0, 0><<<dim3(HWP / BN, CI / BM, BATCH), 256>>>(
        g_w, xp, g, g_b, CI, HWP, CIN,
        0, (size_t)CIN * HWP, (size_t)CI * HWP, 1.0f);

    // 5. scores = theta^T @ phi * scale   [4096 x 1024] per batch
    const float scale = 1.0f / sqrtf((float)CI);
    gemm_kernel<1, 0><<<dim3(HWP / BN, HW / BM, BATCH), 256>>>(
        theta, phi, attn, nullptr, HW, HWP, CI,
        (size_t)CI * HW, (size_t)CI * HWP, (size_t)HW * HWP, scale);

    // 6. softmax rows
    softmax_kernel<<<BATCH * HW, 256>>>();

    // 7. y = g @ attn^T   [512 x 4096] per batch
    gemm_kernel<0, 1><<<dim3(HW / BN, CI / BM, BATCH), 256>>>(
        g, attn, y, nullptr, CI, HW, HWP,
        (size_t)CI * HWP, (size_t)HW * HWP, (size_t)CI * HW, 1.0f);

    // 8. z = wz_w @ y + wz_b   [1024 x 4096] per batch
    gemm_kernel<0, 0><<<dim3(HW / BN, CIN / BM, BATCH), 256>>>(
        wz_w, y, z, wz_b, CIN, HW, CI,
        0, (size_t)CI * HW, (size_t)CIN * HW, 1.0f);

    // 9. batch-norm statistics
    bn_stats_kernel<<<CIN, 256>>>();

    // 10. out = x + gamma*(z-mean)*rstd + beta
    const size_t total = (size_t)BATCH * CIN * HW;
    final_kernel<<<(int)((total + 255) / 256), 256>>>(x, gamma, beta, out);
}

// round 2
// speedup vs baseline: 2.1125x; 2.1125x over previous
#include <cuda_runtime.h>
#include <math.h>
#include <stdint.h>

#define BATCH 8
#define CIN 1024
#define CI 512
#define HW 4096     // 64*64
#define HWP 1024    // 32*32

// ---- scratch (static device globals; no allocation at runtime) ----
__device__ float d_xp[(size_t)BATCH * CIN * HWP];
__device__ float d_theta[(size_t)BATCH * CI * HW];
__device__ float d_phi[(size_t)BATCH * CI * HWP];
__device__ float d_g[(size_t)BATCH * CI * HWP];
__device__ float d_attn[(size_t)BATCH * HW * HWP];
__device__ float d_y[(size_t)BATCH * CI * HW];
__device__ float d_z[(size_t)BATCH * CIN * HW];
__device__ float d_mean[CIN];
__device__ float d_rstd[CIN];

// ---------------- maxpool 2x2 stride 2 ----------------
__global__ void maxpool_kernel(const float* __restrict__ x) {
    int idx = blockIdx.x * blockDim.x + threadIdx.x;
    if (idx >= BATCH * CIN * HWP) return;
    int j = idx & 31;
    int i = (idx >> 5) & 31;
    int bc = idx >> 10;
    const float* p = x + (size_t)bc * HW + (size_t)(i * 2) * 64 + j * 2;
    float2 r0 = *(const float2*)(p);
    float2 r1 = *(const float2*)(p + 64);
    d_xp[idx] = fmaxf(fmaxf(r0.x, r0.y), fmaxf(r1.x, r1.y));
}

// ---------------- TF32 tensor-core GEMM ----------------
// C[m][n] = alpha * sum_k A(m,k)*B(k,n) + bias[m]
// AMODE 0: A stored [M][K] (k contiguous)   AMODE 1: A stored [K][M] (m contiguous)
// BMODE 0: B stored [K][N] (n contiguous)   BMODE 1: B stored [N][K] (k contiguous)
// Requires M%128==0, N%128==0, K%32==0.
#define BM 128
#define BN 128
#define BK 32
#define SKA 36   // BK + 4 pad: fragment LDS bank = (36*r + c) % 32 = perm -> conflict-free

__device__ __forceinline__ float tf32r(float f) {
    uint32_t u;
    asm("cvt.rna.tf32.f32 %0, %1;" : "=r"(u) : "f"(f));
    return __uint_as_float(u);
}

template <int AMODE, int BMODE>
__global__ void __launch_bounds__(256) mma_gemm(
    const float* __restrict__ A, const float* __restrict__ Bp,
    float* __restrict__ C, const float* __restrict__ bias,
    int M, int N, int K, size_t sA, size_t sB, size_t sC, float alpha)
{
    __shared__ float As[BM * SKA];
    __shared__ float Bs[BN * SKA];

    const int b = blockIdx.z;
    A  += (size_t)b * sA;
    Bp += (size_t)b * sB;
    C  += (size_t)b * sC;

    const int m0 = blockIdx.y * BM;
    const int n0 = blockIdx.x * BN;
    const int tid = threadIdx.x;
    const int wid = tid >> 5;
    const int lane = tid & 31;
    const int wm = wid >> 2;          // 0..1  -> 64-row slab
    const int wn = wid & 3;           // 0..3  -> 32-col slab
    const int qr = lane >> 2;         // 0..7
    const int qc = lane & 3;          // 0..3

    float acc[4][4][4];
#pragma unroll
    for (int mi = 0; mi < 4; mi++)
#pragma unroll
        for (int ni = 0; ni < 4; ni++)
#pragma unroll
            for (int v = 0; v < 4; v++) acc[mi][ni][v] = 0.f;

    for (int k0 = 0; k0 < K; k0 += BK) {
        // ---- load A tile -> As[m][k] ----
        if (AMODE == 0) {
#pragma unroll
            for (int i = 0; i < 4; i++) {
                int l = tid + i * 256;
                int m = l >> 3, k = (l & 7) << 2;
                float4 v = *(const float4*)&A[(size_t)(m0 + m) * K + k0 + k];
                float* s = &As[m * SKA + k];
                s[0] = tf32r(v.x); s[1] = tf32r(v.y); s[2] = tf32r(v.z); s[3] = tf32r(v.w);
            }
        } else {
#pragma unroll
            for (int i = 0; i < 4; i++) {
                int l = tid + i * 256;
                int k = l >> 5, m = (l & 31) << 2;
                float4 v = *(const float4*)&A[(size_t)(k0 + k) * M + m0 + m];
                As[(m + 0) * SKA + k] = tf32r(v.x);
                As[(m + 1) * SKA + k] = tf32r(v.y);
                As[(m + 2) * SKA + k] = tf32r(v.z);
                As[(m + 3) * SKA + k] = tf32r(v.w);
            }
        }
        // ---- load B tile -> Bs[n][k] ----
        if (BMODE == 0) {
#pragma unroll
            for (int i = 0; i < 4; i++) {
                int l = tid + i * 256;
                int k = l >> 5, n = (l & 31) << 2;
                float4 v = *(const float4*)&Bp[(size_t)(k0 + k) * N + n0 + n];
                Bs[(n + 0) * SKA + k] = tf32r(v.x);
                Bs[(n + 1) * SKA + k] = tf32r(v.y);
                Bs[(n + 2) * SKA + k] = tf32r(v.z);
                Bs[(n + 3) * SKA + k] = tf32r(v.w);
            }
        } else {
#pragma unroll
            for (int i = 0; i < 4; i++) {
                int l = tid + i * 256;
                int n = l >> 3, k = (l & 7) << 2;
                float4 v = *(const float4*)&Bp[(size_t)(n0 + n) * K + k0 + k];
                float* s = &Bs[n * SKA + k];
                s[0] = tf32r(v.x); s[1] = tf32r(v.y); s[2] = tf32r(v.z); s[3] = tf32r(v.w);
            }
        }
        __syncthreads();

#pragma unroll
        for (int kk = 0; kk < BK; kk += 8) {
            uint32_t a[4][4], bb[4][2];
#pragma unroll
            for (int mi = 0; mi < 4; mi++) {
                const float* p = &As[(wm * 64 + mi * 16 + qr) * SKA + kk + qc];
                a[mi][0] = __float_as_uint(p[0]);
                a[mi][1] = __float_as_uint(p[8 * SKA]);
                a[mi][2] = __float_as_uint(p[4]);
                a[mi][3] = __float_as_uint(p[8 * SKA + 4]);
            }
#pragma unroll
            for (int ni = 0; ni < 4; ni++) {
                const float* p = &Bs[(wn * 32 + ni * 8 + qr) * SKA + kk + qc];
                bb[ni][0] = __float_as_uint(p[0]);
                bb[ni][1] = __float_as_uint(p[4]);
            }
#pragma unroll
            for (int mi = 0; mi < 4; mi++)
#pragma unroll
                for (int ni = 0; ni < 4; ni++) {
                    asm volatile(
                        "mma.sync.aligned.m16n8k8.row.col.f32.tf32.tf32.f32 "
                        "{%0,%1,%2,%3}, {%4,%5,%6,%7}, {%8,%9}, {%0,%1,%2,%3};\n"
                        : "+f"(acc[mi][ni][0]), "+f"(acc[mi][ni][1]),
                          "+f"(acc[mi][ni][2]), "+f"(acc[mi][ni][3])
                        : "r"(a[mi][0]), "r"(a[mi][1]), "r"(a[mi][2]), "r"(a[mi][3]),
                          "r"(bb[ni][0]), "r"(bb[ni][1]));
                }
        }
        __syncthreads();
    }

    // ---- epilogue ----
#pragma unroll
    for (int mi = 0; mi < 4; mi++) {
        int m = m0 + wm * 64 + mi * 16 + qr;
        float bv0 = bias ? bias[m] : 0.f;
        float bv1 = bias ? bias[m + 8] : 0.f;
#pragma unroll
        for (int ni = 0; ni < 4; ni++) {
            int n = n0 + wn * 32 + ni * 8 + qc * 2;
            float2 r0, r1;
            r0.x = acc[mi][ni][0] * alpha + bv0;
            r0.y = acc[mi][ni][1] * alpha + bv0;
            r1.x = acc[mi][ni][2] * alpha + bv1;
            r1.y = acc[mi][ni][3] * alpha + bv1;
            *(float2*)&C[(size_t)m * N + n] = r0;
            *(float2*)&C[(size_t)(m + 8) * N + n] = r1;
        }
    }
}

// ---------------- row softmax over d_attn (rows of length 1024) ----------------
__global__ void softmax_kernel() {
    size_t row = blockIdx.x;
    float4* p = (float4*)(d_attn + row * HWP);
    int tid = threadIdx.x;  // 256 threads -> 1 float4 each
    float4 v = p[tid];
    float mx = fmaxf(fmaxf(v.x, v.y), fmaxf(v.z, v.w));
#pragma unroll
    for (int o = 16; o > 0; o >>= 1) mx = fmaxf(mx, __shfl_xor_sync(0xffffffffu, mx, o));
    __shared__ float sm[8], sv[8];
    if ((tid & 31) == 0) sm[tid >> 5] = mx;
    __syncthreads();
    if (tid == 0) {
        float t = sm[0];
        for (int i = 1; i < 8; i++) t = fmaxf(t, sm[i]);
        sm[0] = t;
    }
    __syncthreads();
    mx = sm[0];
    v.x = __expf(v.x - mx); v.y = __expf(v.y - mx);
    v.z = __expf(v.z - mx); v.w = __expf(v.w - mx);
    float s = v.x + v.y + v.z + v.w;
#pragma unroll
    for (int o = 16; o > 0; o >>= 1) s += __shfl_xor_sync(0xffffffffu, s, o);
    if ((tid & 31) == 0) sv[tid >> 5] = s;
    __syncthreads();
    if (tid == 0) {
        float t = 0.f;
        for (int i = 0; i < 8; i++) t += sv[i];
        sv[0] = t;
    }
    __syncthreads();
    float inv = 1.f / sv[0];
    v.x *= inv; v.y *= inv; v.z *= inv; v.w *= inv;
    p[tid] = v;
}

// ---------------- BatchNorm batch statistics over d_z ----------------
__global__ void bn_stats_kernel() {
    int c = blockIdx.x;
    int tid = threadIdx.x;  // 256
    float s = 0.f, sq = 0.f;
    for (int b = 0; b < BATCH; b++) {
        const float4* p = (const float4*)(d_z + (size_t)(b * CIN + c) * HW);
        for (int n = tid; n < HW / 4; n += 256) {
            float4 v = p[n];
            s += v.x + v.y + v.z + v.w;
            sq += v.x * v.x + v.y * v.y + v.z * v.z + v.w * v.w;
        }
    }
#pragma unroll
    for (int o = 16; o > 0; o >>= 1) {
        s += __shfl_xor_sync(0xffffffffu, s, o);
        sq += __shfl_xor_sync(0xffffffffu, sq, o);
    }
    __shared__ float ss[8], ssq[8];
    if ((tid & 31) == 0) { ss[tid >> 5] = s; ssq[tid >> 5] = sq; }
    __syncthreads();
    if (tid == 0) {
        float S = 0.f, SQ = 0.f;
        for (int i = 0; i < 8; i++) { S += ss[i]; SQ += ssq[i]; }
        const float inv_n = 1.0f / (float)(BATCH * HW);
        float mean = S * inv_n;
        float var = SQ * inv_n - mean * mean;
        d_mean[c] = mean;
        d_rstd[c] = rsqrtf(var + 1e-5f);
    }
}

// ---------------- final: out = x + gamma*(z-mean)*rstd + beta ----------------
__global__ void final_kernel(const float* __restrict__ x,
                             const float* __restrict__ gamma,
                             const float* __restrict__ beta,
                             float* __restrict__ out) {
    size_t i4 = (size_t)blockIdx.x * blockDim.x + threadIdx.x;
    const size_t total4 = (size_t)BATCH * CIN * HW / 4;
    if (i4 >= total4) return;
    int c = (int)((i4 >> 10) & (CIN - 1));  // (i4*4)/4096 % 1024
    float scale = d_rstd[c] * gamma[c];
    float off = beta[c] - d_mean[c] * scale;
    float4 xv = ((const float4*)x)[i4];
    float4 zv = ((const float4*)d_z)[i4];
    float4 o;
    o.x = xv.x + zv.x * scale + off;
    o.y = xv.y + zv.y * scale + off;
    o.z = xv.z + zv.z * scale + off;
    o.w = xv.w + zv.w * scale + off;
    ((float4*)out)[i4] = o;
}

extern "C" void kernel_launch(void* const* d_in, const int* in_sizes, int n_in,
                              void* d_out, int out_size) {
    const float* x       = (const float*)d_in[0];
    const float* theta_w = (const float*)d_in[1];
    const float* theta_b = (const float*)d_in[2];
    const float* phi_w   = (const float*)d_in[3];
    const float* phi_b   = (const float*)d_in[4];
    const float* g_w     = (const float*)d_in[5];
    const float* g_b     = (const float*)d_in[6];
    const float* wz_w    = (const float*)d_in[7];
    const float* wz_b    = (const float*)d_in[8];
    const float* gamma   = (const float*)d_in[9];
    const float* beta    = (const float*)d_in[10];
    float* out = (float*)d_out;

    float *xp, *theta, *phi, *g, *attn, *y, *z;
    cudaGetSymbolAddress((void**)&xp, d_xp);
    cudaGetSymbolAddress((void**)&theta, d_theta);
    cudaGetSymbolAddress((void**)&phi, d_phi);
    cudaGetSymbolAddress((void**)&g, d_g);
    cudaGetSymbolAddress((void**)&attn, d_attn);
    cudaGetSymbolAddress((void**)&y, d_y);
    cudaGetSymbolAddress((void**)&z, d_z);

    // 1. maxpool
    maxpool_kernel<<<(BATCH * CIN * HWP + 255) / 256, 256>>>(x);

    // 2. theta = theta_w @ x   [512 x 4096] per batch
    mma_gemm<0, 0><<<dim3(HW / BN, CI / BM, BATCH), 256>>>(
        theta_w, x, theta, theta_b, CI, HW, CIN,
        0, (size_t)CIN * HW, (size_t)CI * HW, 1.0f);

    // 3. phi = phi_w @ xp   [512 x 1024] per batch
    mma_gemm<0, 0><<<dim3(HWP / BN, CI / BM, BATCH), 256>>>(
        phi_w, xp, phi, phi_b, CI, HWP, CIN,
        0, (size_t)CIN * HWP, (size_t)CI * HWP, 1.0f);

    // 4. g = g_w @ xp
    mma_gemm<0, 0><<<dim3(HWP / BN, CI / BM, BATCH), 256>>>(
        g_w, xp, g, g_b, CI, HWP, CIN,
        0, (size_t)CIN * HWP, (size_t)CI * HWP, 1.0f);

    // 5. scores = theta^T @ phi * scale   [4096 x 1024] per batch
    const float scale = 1.0f / sqrtf((float)CI);
    mma_gemm<1, 0><<<dim3(HWP / BN, HW / BM, BATCH), 256>>>(
        theta, phi, attn, nullptr, HW, HWP, CI,
        (size_t)CI * HW, (size_t)CI * HWP, (size_t)HW * HWP, scale);

    // 6. softmax rows
    softmax_kernel<<<BATCH * HW, 256>>>();

    // 7. y = g @ attn^T   [512 x 4096] per batch
    mma_gemm<0, 1><<<dim3(HW / BN, CI / BM, BATCH), 256>>>(
        g, attn, y, nullptr, CI, HW, HWP,
        (size_t)CI * HWP, (size_t)HW * HWP, (size_t)CI * HW, 1.0f);

    // 8. z = wz_w @ y + wz_b   [1024 x 4096] per batch
    mma_gemm<0, 0><<<dim3(HW / BN, CIN / BM, BATCH), 256>>>(
        wz_w, y, z, wz_b, CIN, HW, CI,
        0, (size_t)CI * HW, (size_t)CIN * HW, 1.0f);

    // 9. batch-norm statistics
    bn_stats_kernel<<<CIN, 256>>>();

    // 10. out = x + gamma*(z-mean)*rstd + beta
    const size_t total4 = (size_t)BATCH * CIN * HW / 4;
    final_kernel<<<(int)((total4 + 255) / 256), 256>>>(x, gamma, beta, out);
}

// round 3
// speedup vs baseline: 4.0717x; 1.9274x over previous
#include <cuda_runtime.h>
#include <math.h>
#include <stdint.h>

#define BATCH 8
#define CIN 1024
#define CI 512
#define HW 4096     // 64*64
#define HWP 1024    // 32*32
#define WSZ 524288  // all four weight matrices are 512*1024 elements

// ---- scratch (static device globals; no allocation at runtime) ----
__device__ float d_xr[(size_t)BATCH * CIN * HW];      // tf32-rounded copy of x
__device__ float d_xp[(size_t)BATCH * CIN * HWP];
__device__ float d_theta[(size_t)BATCH * CI * HW];
__device__ float d_phi[(size_t)BATCH * CI * HWP];
__device__ float d_g[(size_t)BATCH * CI * HWP];
__device__ float d_attn[(size_t)BATCH * HW * HWP];
__device__ float d_y[(size_t)BATCH * CI * HW];
__device__ float d_z[(size_t)BATCH * CIN * HW];
__device__ float d_w4[4 * WSZ];                       // rounded weights
__device__ float d_mean[CIN];
__device__ float d_rstd[CIN];

__device__ __forceinline__ float tf32r(float f) {
    uint32_t u;
    asm("cvt.rna.tf32.f32 %0, %1;" : "=r"(u) : "f"(f));
    return __uint_as_float(u);
}

__device__ __forceinline__ void cp16(uint32_t dst, const float* src) {
    asm volatile("cp.async.cg.shared.global [%0], [%1], 16;\n" :: "r"(dst), "l"(src));
}

// ---------------- prep: round weights + x to tf32 ----------------
__global__ void round_weights_kernel(const float* __restrict__ w0, const float* __restrict__ w1,
                                     const float* __restrict__ w2, const float* __restrict__ w3) {
    int i = blockIdx.x * blockDim.x + threadIdx.x;
    if (i >= WSZ) return;
    d_w4[0 * WSZ + i] = tf32r(w0[i]);
    d_w4[1 * WSZ + i] = tf32r(w1[i]);
    d_w4[2 * WSZ + i] = tf32r(w2[i]);
    d_w4[3 * WSZ + i] = tf32r(w3[i]);
}

__global__ void round_x_kernel(const float* __restrict__ x) {
    size_t i4 = (size_t)blockIdx.x * blockDim.x + threadIdx.x;
    if (i4 >= (size_t)BATCH * CIN * HW / 4) return;
    float4 v = ((const float4*)x)[i4];
    v.x = tf32r(v.x); v.y = tf32r(v.y); v.z = tf32r(v.z); v.w = tf32r(v.w);
    ((float4*)d_xr)[i4] = v;
}

// ---------------- maxpool 2x2 stride 2 (rounded output) ----------------
__global__ void maxpool_kernel(const float* __restrict__ x) {
    int idx = blockIdx.x * blockDim.x + threadIdx.x;
    if (idx >= BATCH * CIN * HWP) return;
    int j = idx & 31;
    int i = (idx >> 5) & 31;
    int bc = idx >> 10;
    const float* p = x + (size_t)bc * HW + (size_t)(i * 2) * 64 + j * 2;
    float2 r0 = *(const float2*)(p);
    float2 r1 = *(const float2*)(p + 64);
    d_xp[idx] = tf32r(fmaxf(fmaxf(r0.x, r0.y), fmaxf(r1.x, r1.y)));
}

// ---------------- TF32 tensor-core GEMM, cp.async double-buffered ----------------
// C[m][n] = alpha * sum_k A(m,k)*B(k,n) + bias[m]
// AKC=1: A stored [M][K] (k contiguous).  AKC=0: A stored [K][M] (m contiguous).
// BKC=1: B stored [N][K] (k contiguous).  BKC=0: B stored [K][N] (n contiguous).
// CTA tile 128x256, 8 warps (2x4), warp tile 64x64. BK=32. Inputs must be
// pre-rounded to tf32. Requires M%128==0, N%256==0, K%32==0.
#define BM 128
#define BN 256
#define BK 32

template <int AKC, int BKC, int ROUND>
__global__ void __launch_bounds__(256, 1) mma_gemm(
    const float* __restrict__ A, const float* __restrict__ Bp,
    float* __restrict__ C, const float* __restrict__ bias,
    int M, int N, int K, size_t sA, size_t sB, size_t sC, float alpha)
{
    extern __shared__ float smem[];
    const uint32_t sbase = (uint32_t)__cvta_generic_to_shared(smem);

    const int b = blockIdx.z;
    A  += (size_t)b * sA;
    Bp += (size_t)b * sB;
    C  += (size_t)b * sC;

    const int m0 = blockIdx.y * BM;
    const int n0 = blockIdx.x * BN;
    const int tid = threadIdx.x;
    const int wid = tid >> 5;
    const int lane = tid & 31;
    const int wm = wid >> 2;          // 0..1 -> 64-row slab
    const int wn = wid & 3;           // 0..3 -> 64-col slab
    const int qr = lane >> 2;         // 0..7
    const int qc = lane & 3;          // 0..3

    float acc[4][8][4];
#pragma unroll
    for (int mi = 0; mi < 4; mi++)
#pragma unroll
        for (int ni = 0; ni < 8; ni++)
#pragma unroll
            for (int v = 0; v < 4; v++) acc[mi][ni][v] = 0.f;

    const int NT = K / BK;

    // ---- prefetch helper (macro-style lambda) ----
    auto prefetch = [&](int k0, int buf) {
        uint32_t sAb = sbase + buf * 16384;
        uint32_t sBb = sbase + 32768 + buf * 32768;
        if (AKC) {
#pragma unroll
            for (int i = 0; i < 4; i++) {
                int l = tid + i * 256;
                int r = l >> 3, c = l & 7;
                uint32_t dst = sAb + (uint32_t)((r * 32 + ((c ^ (r & 7)) << 2)) * 4);
                cp16(dst, A + (size_t)(m0 + r) * K + k0 + c * 4);
            }
        } else {
#pragma unroll
            for (int i = 0; i < 4; i++) {
                int l = tid + i * 256;
                int k = l >> 5, c = l & 31;
                uint32_t dst = sAb + (uint32_t)((k * 128 + ((c ^ (k & 7)) << 2)) * 4);
                cp16(dst, A + (size_t)(k0 + k) * M + m0 + c * 4);
            }
        }
        if (BKC) {
#pragma unroll
            for (int i = 0; i < 8; i++) {
                int l = tid + i * 256;
                int r = l >> 3, c = l & 7;
                uint32_t dst = sBb + (uint32_t)((r * 32 + ((c ^ (r & 7)) << 2)) * 4);
                cp16(dst, Bp + (size_t)(n0 + r) * K + k0 + c * 4);
            }
        } else {
#pragma unroll
            for (int i = 0; i < 8; i++) {
                int l = tid + i * 256;
                int k = l >> 6, c = l & 63;
                uint32_t dst = sBb + (uint32_t)((k * 256 + ((c ^ (k & 7)) << 2)) * 4);
                cp16(dst, Bp + (size_t)(k0 + k) * N + n0 + c * 4);
            }
        }
    };

    prefetch(0, 0);
    asm volatile("cp.async.commit_group;\n" ::);

    for (int it = 0; it < NT; it++) {
        if (it + 1 < NT) {
            prefetch((it + 1) * BK, (it + 1) & 1);
            asm volatile("cp.async.commit_group;\n" ::);
            asm volatile("cp.async.wait_group 1;\n" ::);
        } else {
            asm volatile("cp.async.wait_group 0;\n" ::);
        }
        __syncthreads();

        const float* As = smem + (it & 1) * 4096;
        const float* Bs = smem + 8192 + (it & 1) * 8192;

#pragma unroll
        for (int kk8 = 0; kk8 < 4; kk8++) {
            uint32_t a[4][4], bb[8][2];
#pragma unroll
            for (int mi = 0; mi < 4; mi++) {
                if (AKC) {
                    int r = wm * 64 + mi * 16 + qr;
                    int w0 = ((2 * kk8) ^ qr) << 2;
                    const float* p = As + r * 32 + qc;
                    a[mi][0] = __float_as_uint(p[w0]);
                    a[mi][1] = __float_as_uint(p[256 + w0]);
                    a[mi][2] = __float_as_uint(p[w0 ^ 4]);
                    a[mi][3] = __float_as_uint(p[256 + (w0 ^ 4)]);
                } else {
                    int m = wm * 64 + mi * 16 + qr;
                    int k = kk8 * 8 + qc;
                    int m4 = m >> 2, mm = m & 3;
                    a[mi][0] = __float_as_uint(As[k * 128 + ((m4 ^ qc) << 2) + mm]);
                    a[mi][1] = __float_as_uint(As[k * 128 + (((m4 + 2) ^ qc) << 2) + mm]);
                    a[mi][2] = __float_as_uint(As[(k + 4) * 128 + ((m4 ^ (qc + 4)) << 2) + mm]);
                    a[mi][3] = __float_as_uint(As[(k + 4) * 128 + (((m4 + 2) ^ (qc + 4)) << 2) + mm]);
                }
            }
#pragma unroll
            for (int ni = 0; ni < 8; ni++) {
                if (BKC) {
                    int r = wn * 64 + ni * 8 + qr;
                    int w0 = ((2 * kk8) ^ qr) << 2;
                    const float* p = Bs + r * 32 + qc;
                    bb[ni][0] = __float_as_uint(p[w0]);
                    bb[ni][1] = __float_as_uint(p[w0 ^ 4]);
                } else {
                    int n = wn * 64 + ni * 8 + qr;
                    int k = kk8 * 8 + qc;
                    int n4 = n >> 2, nn = n & 3;
                    bb[ni][0] = __float_as_uint(Bs[k * 256 + ((n4 ^ qc) << 2) + nn]);
                    bb[ni][1] = __float_as_uint(Bs[(k + 4) * 256 + ((n4 ^ (qc + 4)) << 2) + nn]);
                }
            }
#pragma unroll
            for (int mi = 0; mi < 4; mi++)
#pragma unroll
                for (int ni = 0; ni < 8; ni++) {
                    asm volatile(
                        "mma.sync.aligned.m16n8k8.row.col.f32.tf32.tf32.f32 "
                        "{%0,%1,%2,%3}, {%4,%5,%6,%7}, {%8,%9}, {%0,%1,%2,%3};\n"
                        : "+f"(acc[mi][ni][0]), "+f"(acc[mi][ni][1]),
                          "+f"(acc[mi][ni][2]), "+f"(acc[mi][ni][3])
                        : "r"(a[mi][0]), "r"(a[mi][1]), "r"(a[mi][2]), "r"(a[mi][3]),
                          "r"(bb[ni][0]), "r"(bb[ni][1]));
                }
        }
        __syncthreads();
    }

    // ---- epilogue ----
#pragma unroll
    for (int mi = 0; mi < 4; mi++) {
        int m = m0 + wm * 64 + mi * 16 + qr;
        float bv0 = bias ? bias[m] : 0.f;
        float bv1 = bias ? bias[m + 8] : 0.f;
#pragma unroll
        for (int ni = 0; ni < 8; ni++) {
            int n = n0 + wn * 64 + ni * 8 + qc * 2;
            float2 r0, r1;
            r0.x = acc[mi][ni][0] * alpha + bv0;
            r0.y = acc[mi][ni][1] * alpha + bv0;
            r1.x = acc[mi][ni][2] * alpha + bv1;
            r1.y = acc[mi][ni][3] * alpha + bv1;
            if (ROUND) {
                r0.x = tf32r(r0.x); r0.y = tf32r(r0.y);
                r1.x = tf32r(r1.x); r1.y = tf32r(r1.y);
            }
            *(float2*)&C[(size_t)m * N + n] = r0;
            *(float2*)&C[(size_t)(m + 8) * N + n] = r1;
        }
    }
}

// ---------------- row softmax over d_attn (rows of length 1024, rounded out) ----------------
__global__ void softmax_kernel() {
    size_t row = blockIdx.x;
    float4* p = (float4*)(d_attn + row * HWP);
    int tid = threadIdx.x;  // 256 threads -> 1 float4 each
    float4 v = p[tid];
    float mx = fmaxf(fmaxf(v.x, v.y), fmaxf(v.z, v.w));
#pragma unroll
    for (int o = 16; o > 0; o >>= 1) mx = fmaxf(mx, __shfl_xor_sync(0xffffffffu, mx, o));
    __shared__ float sm[8], sv[8];
    if ((tid & 31) == 0) sm[tid >> 5] = mx;
    __syncthreads();
    if (tid == 0) {
        float t = sm[0];
        for (int i = 1; i < 8; i++) t = fmaxf(t, sm[i]);
        sm[0] = t;
    }
    __syncthreads();
    mx = sm[0];
    v.x = __expf(v.x - mx); v.y = __expf(v.y - mx);
    v.z = __expf(v.z - mx); v.w = __expf(v.w - mx);
    float s = v.x + v.y + v.z + v.w;
#pragma unroll
    for (int o = 16; o > 0; o >>= 1) s += __shfl_xor_sync(0xffffffffu, s, o);
    if ((tid & 31) == 0) sv[tid >> 5] = s;
    __syncthreads();
    if (tid == 0) {
        float t = 0.f;
        for (int i = 0; i < 8; i++) t += sv[i];
        sv[0] = t;
    }
    __syncthreads();
    float inv = 1.f / sv[0];
    v.x = tf32r(v.x * inv); v.y = tf32r(v.y * inv);
    v.z = tf32r(v.z * inv); v.w = tf32r(v.w * inv);
    p[tid] = v;
}

// ---------------- BatchNorm batch statistics over d_z ----------------
__global__ void bn_stats_kernel() {
    int c = blockIdx.x;
    int tid = threadIdx.x;  // 256
    float s = 0.f, sq = 0.f;
    for (int b = 0; b < BATCH; b++) {
        const float4* p = (const float4*)(d_z + (size_t)(b * CIN + c) * HW);
        for (int n = tid; n < HW / 4; n += 256) {
            float4 v = p[n];
            s += v.x + v.y + v.z + v.w;
            sq += v.x * v.x + v.y * v.y + v.z * v.z + v.w * v.w;
        }
    }
#pragma unroll
    for (int o = 16; o > 0; o >>= 1) {
        s += __shfl_xor_sync(0xffffffffu, s, o);
        sq += __shfl_xor_sync(0xffffffffu, sq, o);
    }
    __shared__ float ss[8], ssq[8];
    if ((tid & 31) == 0) { ss[tid >> 5] = s; ssq[tid >> 5] = sq; }
    __syncthreads();
    if (tid == 0) {
        float S = 0.f, SQ = 0.f;
        for (int i = 0; i < 8; i++) { S += ss[i]; SQ += ssq[i]; }
        const float inv_n = 1.0f / (float)(BATCH * HW);
        float mean = S * inv_n;
        float var = SQ * inv_n - mean * mean;
        d_mean[c] = mean;
        d_rstd[c] = rsqrtf(var + 1e-5f);
    }
}

// ---------------- final: out = x + gamma*(z-mean)*rstd + beta ----------------
__global__ void final_kernel(const float* __restrict__ x,
                             const float* __restrict__ gamma,
                             const float* __restrict__ beta,
                             float* __restrict__ out) {
    size_t i4 = (size_t)blockIdx.x * blockDim.x + threadIdx.x;
    const size_t total4 = (size_t)BATCH * CIN * HW / 4;
    if (i4 >= total4) return;
    int c = (int)((i4 >> 10) & (CIN - 1));
    float scale = d_rstd[c] * gamma[c];
    float off = beta[c] - d_mean[c] * scale;
    float4 xv = ((const float4*)x)[i4];
    float4 zv = ((const float4*)d_z)[i4];
    float4 o;
    o.x = xv.x + zv.x * scale + off;
    o.y = xv.y + zv.y * scale + off;
    o.z = xv.z + zv.z * scale + off;
    o.w = xv.w + zv.w * scale + off;
    ((float4*)out)[i4] = o;
}

#define SMEM_BYTES 98304

extern "C" void kernel_launch(void* const* d_in, const int* in_sizes, int n_in,
                              void* d_out, int out_size) {
    const float* x       = (const float*)d_in[0];
    const float* theta_w = (const float*)d_in[1];
    const float* theta_b = (const float*)d_in[2];
    const float* phi_w   = (const float*)d_in[3];
    const float* phi_b   = (const float*)d_in[4];
    const float* g_w     = (const float*)d_in[5];
    const float* g_b     = (const float*)d_in[6];
    const float* wz_w    = (const float*)d_in[7];
    const float* wz_b    = (const float*)d_in[8];
    const float* gamma   = (const float*)d_in[9];
    const float* beta    = (const float*)d_in[10];
    float* out = (float*)d_out;

    float *xr, *xp, *theta, *phi, *g, *attn, *y, *z, *w4;
    cudaGetSymbolAddress((void**)&xr, d_xr);
    cudaGetSymbolAddress((void**)&xp, d_xp);
    cudaGetSymbolAddress((void**)&theta, d_theta);
    cudaGetSymbolAddress((void**)&phi, d_phi);
    cudaGetSymbolAddress((void**)&g, d_g);
    cudaGetSymbolAddress((void**)&attn, d_attn);
    cudaGetSymbolAddress((void**)&y, d_y);
    cudaGetSymbolAddress((void**)&z, d_z);
    cudaGetSymbolAddress((void**)&w4, d_w4);

    cudaFuncSetAttribute(mma_gemm<1, 0, 1>, cudaFuncAttributeMaxDynamicSharedMemorySize, SMEM_BYTES);
    cudaFuncSetAttribute(mma_gemm<0, 0, 0>, cudaFuncAttributeMaxDynamicSharedMemorySize, SMEM_BYTES);
    cudaFuncSetAttribute(mma_gemm<1, 1, 1>, cudaFuncAttributeMaxDynamicSharedMemorySize, SMEM_BYTES);
    cudaFuncSetAttribute(mma_gemm<1, 0, 0>, cudaFuncAttributeMaxDynamicSharedMemorySize, SMEM_BYTES);

    // 0. prep: round weights and x to tf32
    round_weights_kernel<<<(WSZ + 255) / 256, 256>>>(theta_w, phi_w, g_w, wz_w);
    const size_t total4 = (size_t)BATCH * CIN * HW / 4;
    round_x_kernel<<<(int)((total4 + 255) / 256), 256>>>(x);

    // 1. maxpool (rounded)
    maxpool_kernel<<<(BATCH * CIN * HWP + 255) / 256, 256>>>(x);

    // 2. theta = theta_w @ xr   [512 x 4096] per batch  (A KC, B NC, round)
    mma_gemm<1, 0, 1><<<dim3(HW / BN, CI / BM, BATCH), 256, SMEM_BYTES>>>(
        w4 + 0 * WSZ, xr, theta, theta_b, CI, HW, CIN,
        0, (size_t)CIN * HW, (size_t)CI * HW, 1.0f);

    // 3. phi = phi_w @ xp   [512 x 1024] per batch
    mma_gemm<1, 0, 1><<<dim3(HWP / BN, CI / BM, BATCH), 256, SMEM_BYTES>>>(
        w4 + 1 * WSZ, xp, phi, phi_b, CI, HWP, CIN,
        0, (size_t)CIN * HWP, (size_t)CI * HWP, 1.0f);

    // 4. g = g_w @ xp
    mma_gemm<1, 0, 1><<<dim3(HWP / BN, CI / BM, BATCH), 256, SMEM_BYTES>>>(
        w4 + 2 * WSZ, xp, g, g_b, CI, HWP, CIN,
        0, (size_t)CIN * HWP, (size_t)CI * HWP, 1.0f);

    // 5. scores = theta^T @ phi * scale   [4096 x 1024] per batch (A NC, B NC)
    const float scale = 1.0f / sqrtf((float)CI);
    mma_gemm<0, 0, 0><<<dim3(HWP / BN, HW / BM, BATCH), 256, SMEM_BYTES>>>(
        theta, phi, attn, nullptr, HW, HWP, CI,
        (size_t)CI * HW, (size_t)CI * HWP, (size_t)HW * HWP, scale);

    // 6. softmax rows (rounded output)
    softmax_kernel<<<BATCH * HW, 256>>>();

    // 7. y = g @ attn^T   [512 x 4096] per batch (A KC, B KC, round)
    mma_gemm<1, 1, 1><<<dim3(HW / BN, CI / BM, BATCH), 256, SMEM_BYTES>>>(
        g, attn, y, nullptr, CI, HW, HWP,
        (size_t)CI * HWP, (size_t)HW * HWP, (size_t)CI * HW, 1.0f);

    // 8. z = wz_w @ y + wz_b   [1024 x 4096] per batch (A KC, B NC, no round)
    mma_gemm<1, 0, 0><<<dim3(HW / BN, CIN / BM, BATCH), 256, SMEM_BYTES>>>(
        w4 + 3 * WSZ, y, z, wz_b, CIN, HW, CI,
        0, (size_t)CI * HW, (size_t)CIN * HW, 1.0f);

    // 9. batch-norm statistics
    bn_stats_kernel<<<CIN, 256>>>();

    // 10. out = x + gamma*(z-mean)*rstd + beta
    final_kernel<<<(int)((total4 + 255) / 256), 256>>>(x, gamma, beta, out);
}

// round 8
// speedup vs baseline: 6.0810x; 1.4935x over previous
#include <cuda_runtime.h>
#include <cuda_fp16.h>
#include <math.h>
#include <stdint.h>

#define BATCH 8
#define CIN 1024
#define CI 512
#define HW 4096     // 64*64
#define HWP 1024    // 32*32
#define WSZ 524288  // each weight matrix is 512*1024 elements

// ---- scratch (static device globals; no runtime allocation) ----
// Activations stored [rows][channels], channels (=K) contiguous, fp16.
__device__ __half d_xTh[(size_t)BATCH * HW * CIN];
__device__ __half d_xpTh[(size_t)BATCH * HWP * CIN];
__device__ __half d_thetaTh[(size_t)BATCH * HW * CI];
__device__ __half d_phiTh[(size_t)BATCH * HWP * CI];
__device__ __half d_Gh[(size_t)BATCH * CI * HWP];      // [CI][HWP] per batch
__device__ __half d_attnh[(size_t)BATCH * HW * HWP];
__device__ __half d_yTh[(size_t)BATCH * HW * CI];
__device__ float  d_zT[(size_t)BATCH * HW * CIN];      // fp32 for BN
__device__ __half d_w4h[4 * WSZ];
__device__ float d_psum[64][CIN];
__device__ float d_psq[64][CIN];
__device__ float d_mean[CIN];
__device__ float d_rstd[CIN];

__device__ __forceinline__ void cp16(uint32_t dst, const void* src) {
    asm volatile("cp.async.cg.shared.global [%0], [%1], 16;\n" :: "r"(dst), "l"(src));
}

// ---------------- prep kernels ----------------
__global__ void round_weights_kernel(const float* __restrict__ w0, const float* __restrict__ w1,
                                     const float* __restrict__ w2, const float* __restrict__ w3) {
    int i = blockIdx.x * blockDim.x + threadIdx.x;
    if (i >= WSZ) return;
    d_w4h[0 * WSZ + i] = __float2half_rn(w0[i]);
    d_w4h[1 * WSZ + i] = __float2half_rn(w1[i]);
    d_w4h[2 * WSZ + i] = __float2half_rn(w2[i]);
    d_w4h[3 * WSZ + i] = __float2half_rn(w3[i]);
}

// xTh[b][hw][c] = fp16(x[b][c][hw]) via 32x32 tiled transpose
__global__ void transpose_x_kernel(const float* __restrict__ x) {
    __shared__ float s[32][33];
    int b = blockIdx.z;
    int hw0 = blockIdx.x * 32, c0 = blockIdx.y * 32;
    int tx = threadIdx.x & 31, ty = threadIdx.x >> 5;  // 256 threads: 32x8
#pragma unroll
    for (int k = 0; k < 4; k++)
        s[ty + 8 * k][tx] = x[((size_t)(b * CIN) + c0 + ty + 8 * k) * HW + hw0 + tx];
    __syncthreads();
#pragma unroll
    for (int k = 0; k < 4; k++)
        d_xTh[((size_t)(b * HW) + hw0 + ty + 8 * k) * CIN + c0 + tx] =
            __float2half_rn(s[tx][ty + 8 * k]);
}

// maxpool 2x2 s2 + transpose -> xpTh[b][p][c] fp16
__global__ void maxpool_t_kernel(const float* __restrict__ x) {
    __shared__ float s[32][129];
    int b = blockIdx.z;
    int i = blockIdx.x;        // pooled row 0..31 (covers x rows 2i, 2i+1)
    int c0 = blockIdx.y * 32;
    int tid = threadIdx.x;     // 256
#pragma unroll
    for (int l = 0; l < 16; l++) {
        int idx = tid + l * 256;
        int c = idx >> 7, e = idx & 127;
        s[c][e] = x[((size_t)(b * CIN) + c0 + c) * HW + i * 128 + e];
    }
    __syncthreads();
#pragma unroll
    for (int l = 0; l < 4; l++) {
        int o = tid + l * 256;
        int p = o >> 5, c = o & 31;
        float v = fmaxf(fmaxf(s[c][2 * p], s[c][2 * p + 1]),
                        fmaxf(s[c][64 + 2 * p], s[c][64 + 2 * p + 1]));
        d_xpTh[((size_t)(b * HWP) + i * 32 + p) * CIN + c0 + c] = __float2half_rn(v);
    }
}

// ---------------- fp16 tensor-core GEMM ----------------
// C[M,N] = alpha * A[M,K] . B[N,K]^T + bias;  K contiguous on both operands, fp16.
// CTA tile 128x256, 8 warps (2x4), warp tile 64x64, BK=64 halves (128B rows).
// BIASM: bias indexed by M (else by N). OUTF32: C is float (else __half).
#define HSM_A_STAGE 16384
#define HSM_B_OFF   32768
#define HSM_B_STAGE 32768
#define HSM_TOTAL   98304

template <int BIASM, int OUTF32>
__global__ void __launch_bounds__(256, 1) hgemm(
    const __half* __restrict__ A, const __half* __restrict__ Bp,
    void* __restrict__ Cv, const float* __restrict__ bias,
    int M, int N, int K, size_t sA, size_t sB, size_t sC, float alpha)
{
    extern __shared__ char smem[];
    uint32_t sb;
    asm("{ .reg .u64 t; cvta.to.shared.u64 t, %1; cvt.u32.u64 %0, t; }" : "=r"(sb) : "l"(smem));

    const int b = blockIdx.z;
    A  += (size_t)b * sA;
    Bp += (size_t)b * sB;

    const int m0 = blockIdx.y * 128;
    const int n0 = blockIdx.x * 256;
    const int tid = threadIdx.x;
    const int wid = tid >> 5;
    const int lane = tid & 31;
    const int wm = wid >> 2;
    const int wn = wid & 3;

    const int g = lane >> 3;
    const int rr = lane & 7;
    const int row_off = ((g & 1) << 3) + rr;
    const int chunk_g = g >> 1;

    float acc[4][8][4];
#pragma unroll
    for (int mi = 0; mi < 4; mi++)
#pragma unroll
        for (int ni = 0; ni < 8; ni++)
#pragma unroll
            for (int v = 0; v < 4; v++) acc[mi][ni][v] = 0.f;

    const int NT = K / 64;

    auto prefetch = [&](int it, int buf) {
        const int k0 = it * 64;
        uint32_t sAb = sb + buf * HSM_A_STAGE;
        uint32_t sBb = sb + HSM_B_OFF + buf * HSM_B_STAGE;
#pragma unroll
        for (int i = 0; i < 4; i++) {
            int l = tid + i * 256;
            int r = l >> 3, c = l & 7;
            cp16(sAb + r * 128 + ((c ^ (r & 7)) << 4),
                 A + (size_t)(m0 + r) * K + k0 + c * 8);
        }
#pragma unroll
        for (int i = 0; i < 8; i++) {
            int l = tid + i * 256;
            int r = l >> 3, c = l & 7;
            cp16(sBb + r * 128 + ((c ^ (r & 7)) << 4),
                 Bp + (size_t)(n0 + r) * K + k0 + c * 8);
        }
    };

    prefetch(0, 0);
    asm volatile("cp.async.commit_group;\n" ::);

    for (int it = 0; it < NT; it++) {
        if (it + 1 < NT) {
            prefetch(it + 1, (it + 1) & 1);
            asm volatile("cp.async.commit_group;\n" ::);
            asm volatile("cp.async.wait_group 1;\n" ::);
        } else {
            asm volatile("cp.async.wait_group 0;\n" ::);
        }
        __syncthreads();

        const uint32_t sA = sb + (it & 1) * HSM_A_STAGE;
        const uint32_t sB = sb + HSM_B_OFF + (it & 1) * HSM_B_STAGE;

#pragma unroll
        for (int kk = 0; kk < 4; kk++) {
            uint32_t af[4][4], bf[4][4];
#pragma unroll
            for (int mi = 0; mi < 4; mi++) {
                int m_loc = wm * 64 + mi * 16 + row_off;
                int chunk = kk * 2 + chunk_g;
                uint32_t addr = sA + m_loc * 128 + ((chunk ^ (m_loc & 7)) << 4);
                asm volatile("ldmatrix.sync.aligned.m8n8.x4.shared.b16 {%0,%1,%2,%3}, [%4];"
                             : "=r"(af[mi][0]), "=r"(af[mi][1]),
                               "=r"(af[mi][2]), "=r"(af[mi][3])
                             : "r"(addr));
            }
#pragma unroll
            for (int np = 0; np < 4; np++) {
                int n_loc = wn * 64 + np * 16 + row_off;
                int chunk = kk * 2 + chunk_g;
                uint32_t addr = sB + n_loc * 128 + ((chunk ^ (n_loc & 7)) << 4);
                asm volatile("ldmatrix.sync.aligned.m8n8.x4.shared.b16 {%0,%1,%2,%3}, [%4];"
                             : "=r"(bf[np][0]), "=r"(bf[np][1]),
                               "=r"(bf[np][2]), "=r"(bf[np][3])
                             : "r"(addr));
            }
#pragma unroll
            for (int mi = 0; mi < 4; mi++)
#pragma unroll
                for (int ni = 0; ni < 8; ni++) {
                    uint32_t b0 = bf[ni >> 1][(ni & 1)];
                    uint32_t b1 = bf[ni >> 1][2 + (ni & 1)];
                    asm volatile(
                        "mma.sync.aligned.m16n8k16.row.col.f32.f16.f16.f32 "
                        "{%0,%1,%2,%3}, {%4,%5,%6,%7}, {%8,%9}, {%0,%1,%2,%3};\n"
                        : "+f"(acc[mi][ni][0]), "+f"(acc[mi][ni][1]),
                          "+f"(acc[mi][ni][2]), "+f"(acc[mi][ni][3])
                        : "r"(af[mi][0]), "r"(af[mi][1]), "r"(af[mi][2]), "r"(af[mi][3]),
                          "r"(b0), "r"(b1));
                }
        }
        __syncthreads();
    }

    // ---- epilogue ----
    float* Cf = (float*)Cv + (size_t)b * sC;
    __half* Ch = (__half*)Cv + (size_t)b * sC;
#pragma unroll
    for (int mi = 0; mi < 4; mi++) {
        int m = m0 + wm * 64 + mi * 16 + (lane >> 2);
        float bm0 = 0.f, bm1 = 0.f;
        if (BIASM && bias) { bm0 = bias[m]; bm1 = bias[m + 8]; }
#pragma unroll
        for (int ni = 0; ni < 8; ni++) {
            int n = n0 + wn * 64 + ni * 8 + (lane & 3) * 2;
            float v0 = acc[mi][ni][0] * alpha;
            float v1 = acc[mi][ni][1] * alpha;
            float v2 = acc[mi][ni][2] * alpha;
            float v3 = acc[mi][ni][3] * alpha;
            if (BIASM) {
                v0 += bm0; v1 += bm0; v2 += bm1; v3 += bm1;
            } else if (bias) {
                float bn0 = bias[n], bn1 = bias[n + 1];
                v0 += bn0; v1 += bn1; v2 += bn0; v3 += bn1;
            }
            if (OUTF32) {
                *(float2*)&Cf[(size_t)m * N + n] = make_float2(v0, v1);
                *(float2*)&Cf[(size_t)(m + 8) * N + n] = make_float2(v2, v3);
            } else {
                *(__half2*)&Ch[(size_t)m * N + n] = __floats2half2_rn(v0, v1);
                *(__half2*)&Ch[(size_t)(m + 8) * N + n] = __floats2half2_rn(v2, v3);
            }
        }
    }
}

// ---------------- row softmax over d_attnh (rows of 1024 fp16) ----------------
__global__ void softmax_kernel() {
    size_t row = blockIdx.x;
    uint2* p = (uint2*)(d_attnh + row * HWP);
    int tid = threadIdx.x;  // 256 threads, 4 halves each
    uint2 u = p[tid];
    float2 f01 = __half22float2(*(__half2*)&u.x);
    float2 f23 = __half22float2(*(__half2*)&u.y);
    float mx = fmaxf(fmaxf(f01.x, f01.y), fmaxf(f23.x, f23.y));
#pragma unroll
    for (int o = 16; o > 0; o >>= 1) mx = fmaxf(mx, __shfl_xor_sync(0xffffffffu, mx, o));
    __shared__ float sm[8], sv[8];
    if ((tid & 31) == 0) sm[tid >> 5] = mx;
    __syncthreads();
    if (tid == 0) {
        float t = sm[0];
        for (int i = 1; i < 8; i++) t = fmaxf(t, sm[i]);
        sm[0] = t;
    }
    __syncthreads();
    mx = sm[0];
    f01.x = __expf(f01.x - mx); f01.y = __expf(f01.y - mx);
    f23.x = __expf(f23.x - mx); f23.y = __expf(f23.y - mx);
    float s = f01.x + f01.y + f23.x + f23.y;
#pragma unroll
    for (int o = 16; o > 0; o >>= 1) s += __shfl_xor_sync(0xffffffffu, s, o);
    if ((tid & 31) == 0) sv[tid >> 5] = s;
    __syncthreads();
    if (tid == 0) {
        float t = 0.f;
        for (int i = 0; i < 8; i++) t += sv[i];
        sv[0] = t;
    }
    __syncthreads();
    float inv = 1.f / sv[0];
    __half2 h0 = __floats2half2_rn(f01.x * inv, f01.y * inv);
    __half2 h1 = __floats2half2_rn(f23.x * inv, f23.y * inv);
    u.x = *(uint32_t*)&h0; u.y = *(uint32_t*)&h1;
    p[tid] = u;
}

// ---------------- BN stats over zT fp32 [B*HW][CIN] ----------------
__global__ void bn_partial_kernel() {
    int c = blockIdx.x * 256 + threadIdx.x;
    int rb = blockIdx.y;  // 0..63, 512 rows each
    float s = 0.f, sq = 0.f;
    const float* base = d_zT + (size_t)rb * 512 * CIN + c;
    for (int r = 0; r < 512; r++) {
        float v = base[(size_t)r * CIN];
        s += v;
        sq += v * v;
    }
    d_psum[rb][c] = s;
    d_psq[rb][c] = sq;
}

__global__ void bn_final_kernel() {
    int c = blockIdx.x * 256 + threadIdx.x;
    float s = 0.f, sq = 0.f;
    for (int i = 0; i < 64; i++) { s += d_psum[i][c]; sq += d_psq[i][c]; }
    const float inv_n = 1.0f / (float)(BATCH * HW);
    float mean = s * inv_n;
    float var = sq * inv_n - mean * mean;
    d_mean[c] = mean;
    d_rstd[c] = rsqrtf(var + 1e-5f);
}

// ---------------- final: out[b][c][hw] = x + norm(zT[b][hw][c]) ----------------
__global__ void final_kernel(const float* __restrict__ x,
                             const float* __restrict__ gamma,
                             const float* __restrict__ beta,
                             float* __restrict__ out) {
    __shared__ float s[32][33];
    int b = blockIdx.z;
    int hw0 = blockIdx.x * 32, c0 = blockIdx.y * 32;
    int tx = threadIdx.x & 31, ty = threadIdx.x >> 5;
#pragma unroll
    for (int k = 0; k < 4; k++)
        s[ty + 8 * k][tx] = d_zT[((size_t)(b * HW) + hw0 + ty + 8 * k) * CIN + c0 + tx];
    __syncthreads();
#pragma unroll
    for (int k = 0; k < 4; k++) {
        int c = c0 + ty + 8 * k;
        size_t o = ((size_t)(b * CIN) + c) * HW + hw0 + tx;
        float sc = d_rstd[c] * gamma[c];
        float off = beta[c] - d_mean[c] * sc;
        out[o] = x[o] + s[tx][ty + 8 * k] * sc + off;
    }
}

extern "C" void kernel_launch(void* const* d_in, const int* in_sizes, int n_in,
                              void* d_out, int out_size) {
    const float* x       = (const float*)d_in[0];
    const float* theta_b = (const float*)d_in[2];
    const float* phi_b   = (const float*)d_in[4];
    const float* g_b     = (const float*)d_in[6];
    const float* wz_b    = (const float*)d_in[8];
    const float* gamma   = (const float*)d_in[9];
    const float* beta    = (const float*)d_in[10];
    float* out = (float*)d_out;

    __half *xTh, *xpTh, *thetaTh, *phiTh, *Gh, *attnh, *yTh, *w4h;
    float *zT;
    cudaGetSymbolAddress((void**)&xTh, d_xTh);
    cudaGetSymbolAddress((void**)&xpTh, d_xpTh);
    cudaGetSymbolAddress((void**)&thetaTh, d_thetaTh);
    cudaGetSymbolAddress((void**)&phiTh, d_phiTh);
    cudaGetSymbolAddress((void**)&Gh, d_Gh);
    cudaGetSymbolAddress((void**)&attnh, d_attnh);
    cudaGetSymbolAddress((void**)&yTh, d_yTh);
    cudaGetSymbolAddress((void**)&zT, d_zT);
    cudaGetSymbolAddress((void**)&w4h, d_w4h);

    cudaFuncSetAttribute(hgemm<0, 0>, cudaFuncAttributeMaxDynamicSharedMemorySize, HSM_TOTAL);
    cudaFuncSetAttribute(hgemm<1, 0>, cudaFuncAttributeMaxDynamicSharedMemorySize, HSM_TOTAL);
    cudaFuncSetAttribute(hgemm<0, 1>, cudaFuncAttributeMaxDynamicSharedMemorySize, HSM_TOTAL);

    // 0. prep
    round_weights_kernel<<<(WSZ + 255) / 256, 256>>>(
        (const float*)d_in[1], (const float*)d_in[3], (const float*)d_in[5], (const float*)d_in[7]);
    transpose_x_kernel<<<dim3(HW / 32, CIN / 32, BATCH), 256>>>(x);
    maxpool_t_kernel<<<dim3(32, CIN / 32, BATCH), 256>>>(x);

    // 1. thetaT[HW,CI] = xT . theta_w^T + theta_b (per N)
    hgemm<0, 0><<<dim3(CI / 256, HW / 128, BATCH), 256, HSM_TOTAL>>>(
        xTh, w4h + 0 * WSZ, thetaTh, theta_b,
        HW, CI, CIN, (size_t)HW * CIN, 0, (size_t)HW * CI, 1.0f);

    // 2. phiT[HWP,CI] = xpT . phi_w^T + phi_b (per N)
    hgemm<0, 0><<<dim3(CI / 256, HWP / 128, BATCH), 256, HSM_TOTAL>>>(
        xpTh, w4h + 1 * WSZ, phiTh, phi_b,
        HWP, CI, CIN, (size_t)HWP * CIN, 0, (size_t)HWP * CI, 1.0f);

    // 3. G[CI,HWP] = g_w . xpT^T + g_b (per M)
    hgemm<1, 0><<<dim3(HWP / 256, CI / 128, BATCH), 256, HSM_TOTAL>>>(
        w4h + 2 * WSZ, xpTh, Gh, g_b,
        CI, HWP, CIN, 0, (size_t)HWP * CIN, (size_t)CI * HWP, 1.0f);

    // 4. attn[HW,HWP] = thetaT . phiT^T * scale
    const float scale = 1.0f / sqrtf((float)CI);
    hgemm<0, 0><<<dim3(HWP / 256, HW / 128, BATCH), 256, HSM_TOTAL>>>(
        thetaTh, phiTh, attnh, nullptr,
        HW, HWP, CI, (size_t)HW * CI, (size_t)HWP * CI, (size_t)HW * HWP, scale);

    // 5. softmax
    softmax_kernel<<<BATCH * HW, 256>>>();

    // 6. yT[HW,CI] = attn . G^T
    hgemm<0, 0><<<dim3(CI / 256, HW / 128, BATCH), 256, HSM_TOTAL>>>(
        attnh, Gh, yTh, nullptr,
        HW, CI, HWP, (size_t)HW * HWP, (size_t)CI * HWP, (size_t)HW * CI, 1.0f);

    // 7. zT[HW,CIN] = yT . wz_w^T + wz_b (per N), fp32 out
    hgemm<0, 1><<<dim3(CIN / 256, HW / 128, BATCH), 256, HSM_TOTAL>>>(
        yTh, w4h + 3 * WSZ, zT, wz_b,
        HW, CIN, CI, (size_t)HW * CI, 0, (size_t)HW * CIN, 1.0f);

    // 8. BN stats
    bn_partial_kernel<<<dim3(CIN / 256, 64), 256>>>();
    bn_final_kernel<<<CIN / 256, 256>>>();

    // 9. out = x + gamma*(zT-mean)*rstd + beta (transpose back)
    final_kernel<<<dim3(HW / 32, CIN / 32, BATCH), 256>>>(x, gamma, beta, out);
}

// round 9
// speedup vs baseline: 6.0964x; 1.0025x over previous
#include <cuda_runtime.h>
#include <cuda_fp16.h>
#include <math.h>
#include <stdint.h>

#define BATCH 8
#define CIN 1024
#define CI 512
#define HW 4096     // 64*64
#define HWP 1024    // 32*32
#define WSZ 524288  // each weight matrix is 512*1024 elements

// ---- scratch (static device globals; no runtime allocation) ----
// Activations stored [rows][channels], channels (=K) contiguous, fp16.
__device__ __half d_xTh[(size_t)BATCH * HW * CIN];
__device__ __half d_xpTh[(size_t)BATCH * HWP * CIN];
__device__ __half d_thetaTh[(size_t)BATCH * HW * CI];
__device__ __half d_phiTh[(size_t)BATCH * HWP * CI];
__device__ __half d_Gh[(size_t)BATCH * CI * HWP];      // [CI][HWP] per batch
__device__ __half d_attnh[(size_t)BATCH * HW * HWP];
__device__ __half d_yTh[(size_t)BATCH * HW * CI];
__device__ float  d_zT[(size_t)BATCH * HW * CIN];      // fp32 for BN
__device__ __half d_w4h[4 * WSZ];
__device__ float d_psum[64][CIN];
__device__ float d_psq[64][CIN];
__device__ float d_mean[CIN];
__device__ float d_rstd[CIN];

__device__ __forceinline__ void cp16(uint32_t dst, const void* src) {
    asm volatile("cp.async.cg.shared.global [%0], [%1], 16;\n" :: "r"(dst), "l"(src));
}

// ---------------- prep kernels ----------------
__global__ void round_weights_kernel(const float* __restrict__ w0, const float* __restrict__ w1,
                                     const float* __restrict__ w2, const float* __restrict__ w3) {
    int i = blockIdx.x * blockDim.x + threadIdx.x;
    if (i >= WSZ) return;
    d_w4h[0 * WSZ + i] = __float2half_rn(w0[i]);
    d_w4h[1 * WSZ + i] = __float2half_rn(w1[i]);
    d_w4h[2 * WSZ + i] = __float2half_rn(w2[i]);
    d_w4h[3 * WSZ + i] = __float2half_rn(w3[i]);
}

// xTh[b][hw][c] = fp16(x[b][c][hw]) via 32x32 tiled transpose
__global__ void transpose_x_kernel(const float* __restrict__ x) {
    __shared__ float s[32][33];
    int b = blockIdx.z;
    int hw0 = blockIdx.x * 32, c0 = blockIdx.y * 32;
    int tx = threadIdx.x & 31, ty = threadIdx.x >> 5;  // 256 threads: 32x8
#pragma unroll
    for (int k = 0; k < 4; k++)
        s[ty + 8 * k][tx] = x[((size_t)(b * CIN) + c0 + ty + 8 * k) * HW + hw0 + tx];
    __syncthreads();
#pragma unroll
    for (int k = 0; k < 4; k++)
        d_xTh[((size_t)(b * HW) + hw0 + ty + 8 * k) * CIN + c0 + tx] =
            __float2half_rn(s[tx][ty + 8 * k]);
}

// maxpool 2x2 s2 + transpose -> xpTh[b][p][c] fp16
__global__ void maxpool_t_kernel(const float* __restrict__ x) {
    __shared__ float s[32][129];
    int b = blockIdx.z;
    int i = blockIdx.x;        // pooled row 0..31 (covers x rows 2i, 2i+1)
    int c0 = blockIdx.y * 32;
    int tid = threadIdx.x;     // 256
#pragma unroll
    for (int l = 0; l < 16; l++) {
        int idx = tid + l * 256;
        int c = idx >> 7, e = idx & 127;
        s[c][e] = x[((size_t)(b * CIN) + c0 + c) * HW + i * 128 + e];
    }
    __syncthreads();
#pragma unroll
    for (int l = 0; l < 4; l++) {
        int o = tid + l * 256;
        int p = o >> 5, c = o & 31;
        float v = fmaxf(fmaxf(s[c][2 * p], s[c][2 * p + 1]),
                        fmaxf(s[c][64 + 2 * p], s[c][64 + 2 * p + 1]));
        d_xpTh[((size_t)(b * HWP) + i * 32 + p) * CIN + c0 + c] = __float2half_rn(v);
    }
}

// ---------------- fp16 tensor-core GEMM ----------------
// C[M,N] = alpha * A[M,K] . B[N,K]^T + bias;  K contiguous on both operands, fp16.
// CTA tile 128x256, 8 warps (2x4), warp tile 64x64, BK=64 halves (128B rows).
// 4-stage cp.async pipeline (192KB smem).
// BIASM: bias indexed by M (else by N). OUTF32: C is float (else __half).
#define NSTG 4
#define HSM_A_STAGE 16384
#define HSM_B_OFF   (NSTG * HSM_A_STAGE)
#define HSM_B_STAGE 32768
#define HSM_TOTAL   (NSTG * (HSM_A_STAGE + HSM_B_STAGE))   // 196608

template <int BIASM, int OUTF32>
__global__ void __launch_bounds__(256, 1) hgemm(
    const __half* __restrict__ A, const __half* __restrict__ Bp,
    void* __restrict__ Cv, const float* __restrict__ bias,
    int M, int N, int K, size_t sA, size_t sB, size_t sC, float alpha)
{
    extern __shared__ char smem[];
    uint32_t sb;
    asm("{ .reg .u64 t; cvta.to.shared.u64 t, %1; cvt.u32.u64 %0, t; }" : "=r"(sb) : "l"(smem));

    const int b = blockIdx.z;
    A  += (size_t)b * sA;
    Bp += (size_t)b * sB;

    const int m0 = blockIdx.y * 128;
    const int n0 = blockIdx.x * 256;
    const int tid = threadIdx.x;
    const int wid = tid >> 5;
    const int lane = tid & 31;
    const int wm = wid >> 2;
    const int wn = wid & 3;

    const int g = lane >> 3;
    const int rr = lane & 7;
    const int row_off = ((g & 1) << 3) + rr;
    const int chunk_g = g >> 1;

    float acc[4][8][4];
#pragma unroll
    for (int mi = 0; mi < 4; mi++)
#pragma unroll
        for (int ni = 0; ni < 8; ni++)
#pragma unroll
            for (int v = 0; v < 4; v++) acc[mi][ni][v] = 0.f;

    const int NT = K / 64;

    auto prefetch = [&](int it, int buf) {
        const int k0 = it * 64;
        uint32_t sAb = sb + buf * HSM_A_STAGE;
        uint32_t sBb = sb + HSM_B_OFF + buf * HSM_B_STAGE;
#pragma unroll
        for (int i = 0; i < 4; i++) {
            int l = tid + i * 256;
            int r = l >> 3, c = l & 7;
            cp16(sAb + r * 128 + ((c ^ (r & 7)) << 4),
                 A + (size_t)(m0 + r) * K + k0 + c * 8);
        }
#pragma unroll
        for (int i = 0; i < 8; i++) {
            int l = tid + i * 256;
            int r = l >> 3, c = l & 7;
            cp16(sBb + r * 128 + ((c ^ (r & 7)) << 4),
                 Bp + (size_t)(n0 + r) * K + k0 + c * 8);
        }
    };

    // prime 3 stages (NT >= 4 for all our shapes)
#pragma unroll
    for (int p = 0; p < NSTG - 1; p++) {
        if (p < NT) prefetch(p, p);
        asm volatile("cp.async.commit_group;\n" ::);
    }

    for (int it = 0; it < NT; it++) {
        if (it + NSTG - 1 < NT) prefetch(it + NSTG - 1, (it + NSTG - 1) & (NSTG - 1));
        asm volatile("cp.async.commit_group;\n" ::);
        asm volatile("cp.async.wait_group %0;\n" :: "n"(NSTG - 1));
        __syncthreads();

        const uint32_t sA = sb + (it & (NSTG - 1)) * HSM_A_STAGE;
        const uint32_t sB = sb + HSM_B_OFF + (it & (NSTG - 1)) * HSM_B_STAGE;

#pragma unroll
        for (int kk = 0; kk < 4; kk++) {
            uint32_t af[4][4], bf[4][4];
#pragma unroll
            for (int mi = 0; mi < 4; mi++) {
                int m_loc = wm * 64 + mi * 16 + row_off;
                int chunk = kk * 2 + chunk_g;
                uint32_t addr = sA + m_loc * 128 + ((chunk ^ (m_loc & 7)) << 4);
                asm volatile("ldmatrix.sync.aligned.m8n8.x4.shared.b16 {%0,%1,%2,%3}, [%4];"
                             : "=r"(af[mi][0]), "=r"(af[mi][1]),
                               "=r"(af[mi][2]), "=r"(af[mi][3])
                             : "r"(addr));
            }
#pragma unroll
            for (int np = 0; np < 4; np++) {
                int n_loc = wn * 64 + np * 16 + row_off;
                int chunk = kk * 2 + chunk_g;
                uint32_t addr = sB + n_loc * 128 + ((chunk ^ (n_loc & 7)) << 4);
                asm volatile("ldmatrix.sync.aligned.m8n8.x4.shared.b16 {%0,%1,%2,%3}, [%4];"
                             : "=r"(bf[np][0]), "=r"(bf[np][1]),
                               "=r"(bf[np][2]), "=r"(bf[np][3])
                             : "r"(addr));
            }
#pragma unroll
            for (int mi = 0; mi < 4; mi++)
#pragma unroll
                for (int ni = 0; ni < 8; ni++) {
                    uint32_t b0 = bf[ni >> 1][(ni & 1)];
                    uint32_t b1 = bf[ni >> 1][2 + (ni & 1)];
                    asm volatile(
                        "mma.sync.aligned.m16n8k16.row.col.f32.f16.f16.f32 "
                        "{%0,%1,%2,%3}, {%4,%5,%6,%7}, {%8,%9}, {%0,%1,%2,%3};\n"
                        : "+f"(acc[mi][ni][0]), "+f"(acc[mi][ni][1]),
                          "+f"(acc[mi][ni][2]), "+f"(acc[mi][ni][3])
                        : "r"(af[mi][0]), "r"(af[mi][1]), "r"(af[mi][2]), "r"(af[mi][3]),
                          "r"(b0), "r"(b1));
                }
        }
        __syncthreads();
    }

    // ---- epilogue ----
    float* Cf = (float*)Cv + (size_t)b * sC;
    __half* Ch = (__half*)Cv + (size_t)b * sC;
#pragma unroll
    for (int mi = 0; mi < 4; mi++) {
        int m = m0 + wm * 64 + mi * 16 + (lane >> 2);
        float bm0 = 0.f, bm1 = 0.f;
        if (BIASM && bias) { bm0 = bias[m]; bm1 = bias[m + 8]; }
#pragma unroll
        for (int ni = 0; ni < 8; ni++) {
            int n = n0 + wn * 64 + ni * 8 + (lane & 3) * 2;
            float v0 = acc[mi][ni][0] * alpha;
            float v1 = acc[mi][ni][1] * alpha;
            float v2 = acc[mi][ni][2] * alpha;
            float v3 = acc[mi][ni][3] * alpha;
            if (BIASM) {
                v0 += bm0; v1 += bm0; v2 += bm1; v3 += bm1;
            } else if (bias) {
                float bn0 = bias[n], bn1 = bias[n + 1];
                v0 += bn0; v1 += bn1; v2 += bn0; v3 += bn1;
            }
            if (OUTF32) {
                *(float2*)&Cf[(size_t)m * N + n] = make_float2(v0, v1);
                *(float2*)&Cf[(size_t)(m + 8) * N + n] = make_float2(v2, v3);
            } else {
                *(__half2*)&Ch[(size_t)m * N + n] = __floats2half2_rn(v0, v1);
                *(__half2*)&Ch[(size_t)(m + 8) * N + n] = __floats2half2_rn(v2, v3);
            }
        }
    }
}

// ---------------- row softmax over d_attnh (rows of 1024 fp16) ----------------
__global__ void softmax_kernel() {
    size_t row = blockIdx.x;
    uint2* p = (uint2*)(d_attnh + row * HWP);
    int tid = threadIdx.x;  // 256 threads, 4 halves each
    uint2 u = p[tid];
    float2 f01 = __half22float2(*(__half2*)&u.x);
    float2 f23 = __half22float2(*(__half2*)&u.y);
    float mx = fmaxf(fmaxf(f01.x, f01.y), fmaxf(f23.x, f23.y));
#pragma unroll
    for (int o = 16; o > 0; o >>= 1) mx = fmaxf(mx, __shfl_xor_sync(0xffffffffu, mx, o));
    __shared__ float sm[8], sv[8];
    if ((tid & 31) == 0) sm[tid >> 5] = mx;
    __syncthreads();
    if (tid == 0) {
        float t = sm[0];
        for (int i = 1; i < 8; i++) t = fmaxf(t, sm[i]);
        sm[0] = t;
    }
    __syncthreads();
    mx = sm[0];
    f01.x = __expf(f01.x - mx); f01.y = __expf(f01.y - mx);
    f23.x = __expf(f23.x - mx); f23.y = __expf(f23.y - mx);
    float s = f01.x + f01.y + f23.x + f23.y;
#pragma unroll
    for (int o = 16; o > 0; o >>= 1) s += __shfl_xor_sync(0xffffffffu, s, o);
    if ((tid & 31) == 0) sv[tid >> 5] = s;
    __syncthreads();
    if (tid == 0) {
        float t = 0.f;
        for (int i = 0; i < 8; i++) t += sv[i];
        sv[0] = t;
    }
    __syncthreads();
    float inv = 1.f / sv[0];
    __half2 h0 = __floats2half2_rn(f01.x * inv, f01.y * inv);
    __half2 h1 = __floats2half2_rn(f23.x * inv, f23.y * inv);
    u.x = *(uint32_t*)&h0; u.y = *(uint32_t*)&h1;
    p[tid] = u;
}

// ---------------- BN stats over zT fp32 [B*HW][CIN] ----------------
__global__ void bn_partial_kernel() {
    int c = blockIdx.x * 256 + threadIdx.x;
    int rb = blockIdx.y;  // 0..63, 512 rows each
    float s = 0.f, sq = 0.f;
    const float* base = d_zT + (size_t)rb * 512 * CIN + c;
    for (int r = 0; r < 512; r++) {
        float v = base[(size_t)r * CIN];
        s += v;
        sq += v * v;
    }
    d_psum[rb][c] = s;
    d_psq[rb][c] = sq;
}

__global__ void bn_final_kernel() {
    int c = blockIdx.x * 256 + threadIdx.x;
    float s = 0.f, sq = 0.f;
    for (int i = 0; i < 64; i++) { s += d_psum[i][c]; sq += d_psq[i][c]; }
    const float inv_n = 1.0f / (float)(BATCH * HW);
    float mean = s * inv_n;
    float var = sq * inv_n - mean * mean;
    d_mean[c] = mean;
    d_rstd[c] = rsqrtf(var + 1e-5f);
}

// ---------------- final: out[b][c][hw] = x + norm(zT[b][hw][c]) ----------------
__global__ void final_kernel(const float* __restrict__ x,
                             const float* __restrict__ gamma,
                             const float* __restrict__ beta,
                             float* __restrict__ out) {
    __shared__ float s[32][33];
    int b = blockIdx.z;
    int hw0 = blockIdx.x * 32, c0 = blockIdx.y * 32;
    int tx = threadIdx.x & 31, ty = threadIdx.x >> 5;
#pragma unroll
    for (int k = 0; k < 4; k++)
        s[ty + 8 * k][tx] = d_zT[((size_t)(b * HW) + hw0 + ty + 8 * k) * CIN + c0 + tx];
    __syncthreads();
#pragma unroll
    for (int k = 0; k < 4; k++) {
        int c = c0 + ty + 8 * k;
        size_t o = ((size_t)(b * CIN) + c) * HW + hw0 + tx;
        float sc = d_rstd[c] * gamma[c];
        float off = beta[c] - d_mean[c] * sc;
        out[o] = x[o] + s[tx][ty + 8 * k] * sc + off;
    }
}

extern "C" void kernel_launch(void* const* d_in, const int* in_sizes, int n_in,
                              void* d_out, int out_size) {
    const float* x       = (const float*)d_in[0];
    const float* theta_b = (const float*)d_in[2];
    const float* phi_b   = (const float*)d_in[4];
    const float* g_b     = (const float*)d_in[6];
    const float* wz_b    = (const float*)d_in[8];
    const float* gamma   = (const float*)d_in[9];
    const float* beta    = (const float*)d_in[10];
    float* out = (float*)d_out;

    __half *xTh, *xpTh, *thetaTh, *phiTh, *Gh, *attnh, *yTh, *w4h;
    float *zT;
    cudaGetSymbolAddress((void**)&xTh, d_xTh);
    cudaGetSymbolAddress((void**)&xpTh, d_xpTh);
    cudaGetSymbolAddress((void**)&thetaTh, d_thetaTh);
    cudaGetSymbolAddress((void**)&phiTh, d_phiTh);
    cudaGetSymbolAddress((void**)&Gh, d_Gh);
    cudaGetSymbolAddress((void**)&attnh, d_attnh);
    cudaGetSymbolAddress((void**)&yTh, d_yTh);
    cudaGetSymbolAddress((void**)&zT, d_zT);
    cudaGetSymbolAddress((void**)&w4h, d_w4h);

    cudaFuncSetAttribute(hgemm<0, 0>, cudaFuncAttributeMaxDynamicSharedMemorySize, HSM_TOTAL);
    cudaFuncSetAttribute(hgemm<1, 0>, cudaFuncAttributeMaxDynamicSharedMemorySize, HSM_TOTAL);
    cudaFuncSetAttribute(hgemm<0, 1>, cudaFuncAttributeMaxDynamicSharedMemorySize, HSM_TOTAL);

    // 0. prep
    round_weights_kernel<<<(WSZ + 255) / 256, 256>>>(
        (const float*)d_in[1], (const float*)d_in[3], (const float*)d_in[5], (const float*)d_in[7]);
    transpose_x_kernel<<<dim3(HW / 32, CIN / 32, BATCH), 256>>>(x);
    maxpool_t_kernel<<<dim3(32, CIN / 32, BATCH), 256>>>(x);

    // 1. thetaT[HW,CI] = xT . theta_w^T + theta_b (per N)
    hgemm<0, 0><<<dim3(CI / 256, HW / 128, BATCH), 256, HSM_TOTAL>>>(
        xTh, w4h + 0 * WSZ, thetaTh, theta_b,
        HW, CI, CIN, (size_t)HW * CIN, 0, (size_t)HW * CI, 1.0f);

    // 2. phiT[HWP,CI] = xpT . phi_w^T + phi_b (per N)
    hgemm<0, 0><<<dim3(CI / 256, HWP / 128, BATCH), 256, HSM_TOTAL>>>(
        xpTh, w4h + 1 * WSZ, phiTh, phi_b,
        HWP, CI, CIN, (size_t)HWP * CIN, 0, (size_t)HWP * CI, 1.0f);

    // 3. G[CI,HWP] = g_w . xpT^T + g_b (per M)
    hgemm<1, 0><<<dim3(HWP / 256, CI / 128, BATCH), 256, HSM_TOTAL>>>(
        w4h + 2 * WSZ, xpTh, Gh, g_b,
        CI, HWP, CIN, 0, (size_t)HWP * CIN, (size_t)CI * HWP, 1.0f);

    // 4. attn[HW,HWP] = thetaT . phiT^T * scale
    const float scale = 1.0f / sqrtf((float)CI);
    hgemm<0, 0><<<dim3(HWP / 256, HW / 128, BATCH), 256, HSM_TOTAL>>>(
        thetaTh, phiTh, attnh, nullptr,
        HW, HWP, CI, (size_t)HW * CI, (size_t)HWP * CI, (size_t)HW * HWP, scale);

    // 5. softmax
    softmax_kernel<<<BATCH * HW, 256>>>();

    // 6. yT[HW,CI] = attn . G^T
    hgemm<0, 0><<<dim3(CI / 256, HW / 128, BATCH), 256, HSM_TOTAL>>>(
        attnh, Gh, yTh, nullptr,
        HW, CI, HWP, (size_t)HW * HWP, (size_t)CI * HWP, (size_t)HW * CI, 1.0f);

    // 7. zT[HW,CIN] = yT . wz_w^T + wz_b (per N), fp32 out
    hgemm<0, 1><<<dim3(CIN / 256, HW / 128, BATCH), 256, HSM_TOTAL>>>(
        yTh, w4h + 3 * WSZ, zT, wz_b,
        HW, CIN, CI, (size_t)HW * CI, 0, (size_t)HW * CIN, 1.0f);

    // 8. BN stats
    bn_partial_kernel<<<dim3(CIN / 256, 64), 256>>>();
    bn_final_kernel<<<CIN / 256, 256>>>();

    // 9. out = x + gamma*(zT-mean)*rstd + beta (transpose back)
    final_kernel<<<dim3(HW / 32, CIN / 32, BATCH), 256>>>(x, gamma, beta, out);
}

// round 10
// speedup vs baseline: 6.0974x; 1.0002x over previous
#include <cuda_runtime.h>
#include <cuda_fp16.h>
#include <math.h>
#include <stdint.h>

#define BATCH 8
#define CIN 1024
#define CI 512
#define HW 4096     // 64*64
#define HWP 1024    // 32*32
#define WSZ 524288  // each weight matrix is 512*1024 elements

// ---- scratch (static device globals; no runtime allocation) ----
// Activations stored [rows][channels], channels (=K) contiguous, fp16.
__device__ __half d_xTh[(size_t)BATCH * HW * CIN];
__device__ __half d_xpTh[(size_t)BATCH * HWP * CIN];
__device__ __half d_thetaTh[(size_t)BATCH * HW * CI];
__device__ __half d_phiTh[(size_t)BATCH * HWP * CI];
__device__ __half d_Gh[(size_t)BATCH * CI * HWP];      // [CI][HWP] per batch
__device__ __half d_attnh[(size_t)BATCH * HW * HWP];
__device__ __half d_yTh[(size_t)BATCH * HW * CI];
__device__ float  d_zT[(size_t)BATCH * HW * CIN];      // fp32 for BN
__device__ __half d_w4h[4 * WSZ];
__device__ float d_psum[64][CIN];
__device__ float d_psq[64][CIN];
__device__ float d_mean[CIN];
__device__ float d_rstd[CIN];

__device__ __forceinline__ void cp16(uint32_t dst, const void* src) {
    asm volatile("cp.async.cg.shared.global [%0], [%1], 16;\n" :: "r"(dst), "l"(src));
}

// ---------------- prep kernels ----------------
__global__ void round_weights_kernel(const float* __restrict__ w0, const float* __restrict__ w1,
                                     const float* __restrict__ w2, const float* __restrict__ w3) {
    int i = blockIdx.x * blockDim.x + threadIdx.x;
    if (i >= WSZ) return;
    d_w4h[0 * WSZ + i] = __float2half_rn(w0[i]);
    d_w4h[1 * WSZ + i] = __float2half_rn(w1[i]);
    d_w4h[2 * WSZ + i] = __float2half_rn(w2[i]);
    d_w4h[3 * WSZ + i] = __float2half_rn(w3[i]);
}

// xTh[b][hw][c] = fp16(x[b][c][hw]) via 32x32 tiled transpose
__global__ void transpose_x_kernel(const float* __restrict__ x) {
    __shared__ float s[32][33];
    int b = blockIdx.z;
    int hw0 = blockIdx.x * 32, c0 = blockIdx.y * 32;
    int tx = threadIdx.x & 31, ty = threadIdx.x >> 5;  // 256 threads: 32x8
#pragma unroll
    for (int k = 0; k < 4; k++)
        s[ty + 8 * k][tx] = x[((size_t)(b * CIN) + c0 + ty + 8 * k) * HW + hw0 + tx];
    __syncthreads();
#pragma unroll
    for (int k = 0; k < 4; k++)
        d_xTh[((size_t)(b * HW) + hw0 + ty + 8 * k) * CIN + c0 + tx] =
            __float2half_rn(s[tx][ty + 8 * k]);
}

// maxpool 2x2 s2 + transpose -> xpTh[b][p][c] fp16
__global__ void maxpool_t_kernel(const float* __restrict__ x) {
    __shared__ float s[32][129];
    int b = blockIdx.z;
    int i = blockIdx.x;        // pooled row 0..31 (covers x rows 2i, 2i+1)
    int c0 = blockIdx.y * 32;
    int tid = threadIdx.x;     // 256
#pragma unroll
    for (int l = 0; l < 16; l++) {
        int idx = tid + l * 256;
        int c = idx >> 7, e = idx & 127;
        s[c][e] = x[((size_t)(b * CIN) + c0 + c) * HW + i * 128 + e];
    }
    __syncthreads();
#pragma unroll
    for (int l = 0; l < 4; l++) {
        int o = tid + l * 256;
        int p = o >> 5, c = o & 31;
        float v = fmaxf(fmaxf(s[c][2 * p], s[c][2 * p + 1]),
                        fmaxf(s[c][64 + 2 * p], s[c][64 + 2 * p + 1]));
        d_xpTh[((size_t)(b * HWP) + i * 32 + p) * CIN + c0 + c] = __float2half_rn(v);
    }
}

// ---------------- fp16 tensor-core GEMM ----------------
// C[M,N] = alpha * A[M,K] . B[N,K]^T + bias;  K contiguous on both operands, fp16.
// CTA tile 128x256, 8 warps (2x4), warp tile 64x64, BK=64 halves (128B rows).
// 4-stage cp.async pipeline + ping-pong register fragment pipeline.
// BIASM: bias indexed by M (else by N). OUTF32: C is float (else __half).
#define NSTG 4
#define HSM_A_STAGE 16384
#define HSM_B_OFF   (NSTG * HSM_A_STAGE)
#define HSM_B_STAGE 32768
#define HSM_TOTAL   (NSTG * (HSM_A_STAGE + HSM_B_STAGE))   // 196608

template <int BIASM, int OUTF32>
__global__ void __launch_bounds__(256, 1) hgemm(
    const __half* __restrict__ A, const __half* __restrict__ Bp,
    void* __restrict__ Cv, const float* __restrict__ bias,
    int M, int N, int K, size_t sA, size_t sB, size_t sC, float alpha)
{
    extern __shared__ char smem[];
    uint32_t sb;
    asm("{ .reg .u64 t; cvta.to.shared.u64 t, %1; cvt.u32.u64 %0, t; }" : "=r"(sb) : "l"(smem));

    const int b = blockIdx.z;
    A  += (size_t)b * sA;
    Bp += (size_t)b * sB;

    const int m0 = blockIdx.y * 128;
    const int n0 = blockIdx.x * 256;
    const int tid = threadIdx.x;
    const int wid = tid >> 5;
    const int lane = tid & 31;
    const int wm = wid >> 2;
    const int wn = wid & 3;

    const int g = lane >> 3;
    const int rr = lane & 7;
    const int row_off = ((g & 1) << 3) + rr;
    const int chunk_g = g >> 1;

    // precomputed ldmatrix base addresses (stage 0); stage/kk add offsets later
    uint32_t a_addr[4], b_addr[4];
#pragma unroll
    for (int mi = 0; mi < 4; mi++) {
        int m_loc = wm * 64 + mi * 16 + row_off;
        a_addr[mi] = m_loc * 128 + ((chunk_g ^ (m_loc & 7)) << 4) + (((m_loc & 7) >> 1) << 4) * 0;
        // recompute properly per kk below; store row base + row-parity for xor
        a_addr[mi] = m_loc;  // store row index; full addr computed per kk
    }
#pragma unroll
    for (int np = 0; np < 4; np++) {
        int n_loc = wn * 64 + np * 16 + row_off;
        b_addr[np] = n_loc;
    }

    float acc[4][8][4];
#pragma unroll
    for (int mi = 0; mi < 4; mi++)
#pragma unroll
        for (int ni = 0; ni < 8; ni++)
#pragma unroll
            for (int v = 0; v < 4; v++) acc[mi][ni][v] = 0.f;

    const int NT = K / 64;

    auto prefetch = [&](int it, int buf) {
        const int k0 = it * 64;
        uint32_t sAb = sb + buf * HSM_A_STAGE;
        uint32_t sBb = sb + HSM_B_OFF + buf * HSM_B_STAGE;
#pragma unroll
        for (int i = 0; i < 4; i++) {
            int l = tid + i * 256;
            int r = l >> 3, c = l & 7;
            cp16(sAb + r * 128 + ((c ^ (r & 7)) << 4),
                 A + (size_t)(m0 + r) * K + k0 + c * 8);
        }
#pragma unroll
        for (int i = 0; i < 8; i++) {
            int l = tid + i * 256;
            int r = l >> 3, c = l & 7;
            cp16(sBb + r * 128 + ((c ^ (r & 7)) << 4),
                 Bp + (size_t)(n0 + r) * K + k0 + c * 8);
        }
    };

    uint32_t af[2][4][4], bf[2][4][4];

    auto load_frags = [&](uint32_t sA_, uint32_t sB_, int kk, int pb) {
#pragma unroll
        for (int mi = 0; mi < 4; mi++) {
            int m_loc = (int)a_addr[mi];
            int chunk = kk * 2 + chunk_g;
            uint32_t addr = sA_ + m_loc * 128 + ((chunk ^ (m_loc & 7)) << 4);
            asm volatile("ldmatrix.sync.aligned.m8n8.x4.shared.b16 {%0,%1,%2,%3}, [%4];"
                         : "=r"(af[pb][mi][0]), "=r"(af[pb][mi][1]),
                           "=r"(af[pb][mi][2]), "=r"(af[pb][mi][3])
                         : "r"(addr));
        }
#pragma unroll
        for (int np = 0; np < 4; np++) {
            int n_loc = (int)b_addr[np];
            int chunk = kk * 2 + chunk_g;
            uint32_t addr = sB_ + n_loc * 128 + ((chunk ^ (n_loc & 7)) << 4);
            asm volatile("ldmatrix.sync.aligned.m8n8.x4.shared.b16 {%0,%1,%2,%3}, [%4];"
                         : "=r"(bf[pb][np][0]), "=r"(bf[pb][np][1]),
                           "=r"(bf[pb][np][2]), "=r"(bf[pb][np][3])
                         : "r"(addr));
        }
    };

    auto do_mmas = [&](int pb) {
#pragma unroll
        for (int mi = 0; mi < 4; mi++)
#pragma unroll
            for (int ni = 0; ni < 8; ni++) {
                uint32_t b0 = bf[pb][ni >> 1][(ni & 1)];
                uint32_t b1 = bf[pb][ni >> 1][2 + (ni & 1)];
                asm volatile(
                    "mma.sync.aligned.m16n8k16.row.col.f32.f16.f16.f32 "
                    "{%0,%1,%2,%3}, {%4,%5,%6,%7}, {%8,%9}, {%0,%1,%2,%3};\n"
                    : "+f"(acc[mi][ni][0]), "+f"(acc[mi][ni][1]),
                      "+f"(acc[mi][ni][2]), "+f"(acc[mi][ni][3])
                    : "r"(af[pb][mi][0]), "r"(af[pb][mi][1]),
                      "r"(af[pb][mi][2]), "r"(af[pb][mi][3]),
                      "r"(b0), "r"(b1));
            }
    };

    // prime pipeline stages
#pragma unroll
    for (int p = 0; p < NSTG - 1; p++) {
        if (p < NT) prefetch(p, p);
        asm volatile("cp.async.commit_group;\n" ::);
    }

    for (int it = 0; it < NT; it++) {
        if (it + NSTG - 1 < NT) prefetch(it + NSTG - 1, (it + NSTG - 1) & (NSTG - 1));
        asm volatile("cp.async.commit_group;\n" ::);
        asm volatile("cp.async.wait_group %0;\n" :: "n"(NSTG - 1));
        __syncthreads();

        const uint32_t sA = sb + (it & (NSTG - 1)) * HSM_A_STAGE;
        const uint32_t sB = sb + HSM_B_OFF + (it & (NSTG - 1)) * HSM_B_STAGE;

        // ping-pong fragment pipeline over the 4 kk-steps
        load_frags(sA, sB, 0, 0);
#pragma unroll
        for (int kk = 0; kk < 4; kk++) {
            if (kk < 3) load_frags(sA, sB, kk + 1, (kk + 1) & 1);
            do_mmas(kk & 1);
        }
        __syncthreads();
    }

    // ---- epilogue ----
    float* Cf = (float*)Cv + (size_t)b * sC;
    __half* Ch = (__half*)Cv + (size_t)b * sC;
#pragma unroll
    for (int mi = 0; mi < 4; mi++) {
        int m = m0 + wm * 64 + mi * 16 + (lane >> 2);
        float bm0 = 0.f, bm1 = 0.f;
        if (BIASM && bias) { bm0 = bias[m]; bm1 = bias[m + 8]; }
#pragma unroll
        for (int ni = 0; ni < 8; ni++) {
            int n = n0 + wn * 64 + ni * 8 + (lane & 3) * 2;
            float v0 = acc[mi][ni][0] * alpha;
            float v1 = acc[mi][ni][1] * alpha;
            float v2 = acc[mi][ni][2] * alpha;
            float v3 = acc[mi][ni][3] * alpha;
            if (BIASM) {
                v0 += bm0; v1 += bm0; v2 += bm1; v3 += bm1;
            } else if (bias) {
                float bn0 = bias[n], bn1 = bias[n + 1];
                v0 += bn0; v1 += bn1; v2 += bn0; v3 += bn1;
            }
            if (OUTF32) {
                *(float2*)&Cf[(size_t)m * N + n] = make_float2(v0, v1);
                *(float2*)&Cf[(size_t)(m + 8) * N + n] = make_float2(v2, v3);
            } else {
                *(__half2*)&Ch[(size_t)m * N + n] = __floats2half2_rn(v0, v1);
                *(__half2*)&Ch[(size_t)(m + 8) * N + n] = __floats2half2_rn(v2, v3);
            }
        }
    }
}

// ---------------- row softmax over d_attnh (rows of 1024 fp16) ----------------
__global__ void softmax_kernel() {
    size_t row = blockIdx.x;
    uint2* p = (uint2*)(d_attnh + row * HWP);
    int tid = threadIdx.x;  // 256 threads, 4 halves each
    uint2 u = p[tid];
    float2 f01 = __half22float2(*(__half2*)&u.x);
    float2 f23 = __half22float2(*(__half2*)&u.y);
    float mx = fmaxf(fmaxf(f01.x, f01.y), fmaxf(f23.x, f23.y));
#pragma unroll
    for (int o = 16; o > 0; o >>= 1) mx = fmaxf(mx, __shfl_xor_sync(0xffffffffu, mx, o));
    __shared__ float sm[8], sv[8];
    if ((tid & 31) == 0) sm[tid >> 5] = mx;
    __syncthreads();
    if (tid == 0) {
        float t = sm[0];
        for (int i = 1; i < 8; i++) t = fmaxf(t, sm[i]);
        sm[0] = t;
    }
    __syncthreads();
    mx = sm[0];
    f01.x = __expf(f01.x - mx); f01.y = __expf(f01.y - mx);
    f23.x = __expf(f23.x - mx); f23.y = __expf(f23.y - mx);
    float s = f01.x + f01.y + f23.x + f23.y;
#pragma unroll
    for (int o = 16; o > 0; o >>= 1) s += __shfl_xor_sync(0xffffffffu, s, o);
    if ((tid & 31) == 0) sv[tid >> 5] = s;
    __syncthreads();
    if (tid == 0) {
        float t = 0.f;
        for (int i = 0; i < 8; i++) t += sv[i];
        sv[0] = t;
    }
    __syncthreads();
    float inv = 1.f / sv[0];
    __half2 h0 = __floats2half2_rn(f01.x * inv, f01.y * inv);
    __half2 h1 = __floats2half2_rn(f23.x * inv, f23.y * inv);
    u.x = *(uint32_t*)&h0; u.y = *(uint32_t*)&h1;
    p[tid] = u;
}

// ---------------- BN stats over zT fp32 [B*HW][CIN] ----------------
__global__ void bn_partial_kernel() {
    int c = blockIdx.x * 256 + threadIdx.x;
    int rb = blockIdx.y;  // 0..63, 512 rows each
    float s = 0.f, sq = 0.f;
    const float* base = d_zT + (size_t)rb * 512 * CIN + c;
    for (int r = 0; r < 512; r++) {
        float v = base[(size_t)r * CIN];
        s += v;
        sq += v * v;
    }
    d_psum[rb][c] = s;
    d_psq[rb][c] = sq;
}

__global__ void bn_final_kernel() {
    int c = blockIdx.x * 256 + threadIdx.x;
    float s = 0.f, sq = 0.f;
    for (int i = 0; i < 64; i++) { s += d_psum[i][c]; sq += d_psq[i][c]; }
    const float inv_n = 1.0f / (float)(BATCH * HW);
    float mean = s * inv_n;
    float var = sq * inv_n - mean * mean;
    d_mean[c] = mean;
    d_rstd[c] = rsqrtf(var + 1e-5f);
}

// ---------------- final: out[b][c][hw] = x + norm(zT[b][hw][c]) ----------------
__global__ void final_kernel(const float* __restrict__ x,
                             const float* __restrict__ gamma,
                             const float* __restrict__ beta,
                             float* __restrict__ out) {
    __shared__ float s[32][33];
    int b = blockIdx.z;
    int hw0 = blockIdx.x * 32, c0 = blockIdx.y * 32;
    int tx = threadIdx.x & 31, ty = threadIdx.x >> 5;
#pragma unroll
    for (int k = 0; k < 4; k++)
        s[ty + 8 * k][tx] = d_zT[((size_t)(b * HW) + hw0 + ty + 8 * k) * CIN + c0 + tx];
    __syncthreads();
#pragma unroll
    for (int k = 0; k < 4; k++) {
        int c = c0 + ty + 8 * k;
        size_t o = ((size_t)(b * CIN) + c) * HW + hw0 + tx;
        float sc = d_rstd[c] * gamma[c];
        float off = beta[c] - d_mean[c] * sc;
        out[o] = x[o] + s[tx][ty + 8 * k] * sc + off;
    }
}

extern "C" void kernel_launch(void* const* d_in, const int* in_sizes, int n_in,
                              void* d_out, int out_size) {
    const float* x       = (const float*)d_in[0];
    const float* theta_b = (const float*)d_in[2];
    const float* phi_b   = (const float*)d_in[4];
    const float* g_b     = (const float*)d_in[6];
    const float* wz_b    = (const float*)d_in[8];
    const float* gamma   = (const float*)d_in[9];
    const float* beta    = (const float*)d_in[10];
    float* out = (float*)d_out;

    __half *xTh, *xpTh, *thetaTh, *phiTh, *Gh, *attnh, *yTh, *w4h;
    float *zT;
    cudaGetSymbolAddress((void**)&xTh, d_xTh);
    cudaGetSymbolAddress((void**)&xpTh, d_xpTh);
    cudaGetSymbolAddress((void**)&thetaTh, d_thetaTh);
    cudaGetSymbolAddress((void**)&phiTh, d_phiTh);
    cudaGetSymbolAddress((void**)&Gh, d_Gh);
    cudaGetSymbolAddress((void**)&attnh, d_attnh);
    cudaGetSymbolAddress((void**)&yTh, d_yTh);
    cudaGetSymbolAddress((void**)&zT, d_zT);
    cudaGetSymbolAddress((void**)&w4h, d_w4h);

    cudaFuncSetAttribute(hgemm<0, 0>, cudaFuncAttributeMaxDynamicSharedMemorySize, HSM_TOTAL);
    cudaFuncSetAttribute(hgemm<1, 0>, cudaFuncAttributeMaxDynamicSharedMemorySize, HSM_TOTAL);
    cudaFuncSetAttribute(hgemm<0, 1>, cudaFuncAttributeMaxDynamicSharedMemorySize, HSM_TOTAL);

    // 0. prep
    round_weights_kernel<<<(WSZ + 255) / 256, 256>>>(
        (const float*)d_in[1], (const float*)d_in[3], (const float*)d_in[5], (const float*)d_in[7]);
    transpose_x_kernel<<<dim3(HW / 32, CIN / 32, BATCH), 256>>>(x);
    maxpool_t_kernel<<<dim3(32, CIN / 32, BATCH), 256>>>(x);

    // 1. thetaT[HW,CI] = xT . theta_w^T + theta_b (per N)
    hgemm<0, 0><<<dim3(CI / 256, HW / 128, BATCH), 256, HSM_TOTAL>>>(
        xTh, w4h + 0 * WSZ, thetaTh, theta_b,
        HW, CI, CIN, (size_t)HW * CIN, 0, (size_t)HW * CI, 1.0f);

    // 2. phiT[HWP,CI] = xpT . phi_w^T + phi_b (per N)
    hgemm<0, 0><<<dim3(CI / 256, HWP / 128, BATCH), 256, HSM_TOTAL>>>(
        xpTh, w4h + 1 * WSZ, phiTh, phi_b,
        HWP, CI, CIN, (size_t)HWP * CIN, 0, (size_t)HWP * CI, 1.0f);

    // 3. G[CI,HWP] = g_w . xpT^T + g_b (per M)
    hgemm<1, 0><<<dim3(HWP / 256, CI / 128, BATCH), 256, HSM_TOTAL>>>(
        w4h + 2 * WSZ, xpTh, Gh, g_b,
        CI, HWP, CIN, 0, (size_t)HWP * CIN, (size_t)CI * HWP, 1.0f);

    // 4. attn[HW,HWP] = thetaT . phiT^T * scale
    const float scale = 1.0f / sqrtf((float)CI);
    hgemm<0, 0><<<dim3(HWP / 256, HW / 128, BATCH), 256, HSM_TOTAL>>>(
        thetaTh, phiTh, attnh, nullptr,
        HW, HWP, CI, (size_t)HW * CI, (size_t)HWP * CI, (size_t)HW * HWP, scale);

    // 5. softmax
    softmax_kernel<<<BATCH * HW, 256>>>();

    // 6. yT[HW,CI] = attn . G^T
    hgemm<0, 0><<<dim3(CI / 256, HW / 128, BATCH), 256, HSM_TOTAL>>>(
        attnh, Gh, yTh, nullptr,
        HW, CI, HWP, (size_t)HW * HWP, (size_t)CI * HWP, (size_t)HW * CI, 1.0f);

    // 7. zT[HW,CIN] = yT . wz_w^T + wz_b (per N), fp32 out
    hgemm<0, 1><<<dim3(CIN / 256, HW / 128, BATCH), 256, HSM_TOTAL>>>(
        yTh, w4h + 3 * WSZ, zT, wz_b,
        HW, CIN, CI, (size_t)HW * CI, 0, (size_t)HW * CIN, 1.0f);

    // 8. BN stats
    bn_partial_kernel<<<dim3(CIN / 256, 64), 256>>>();
    bn_final_kernel<<<CIN / 256, 256>>>();

    // 9. out = x + gamma*(zT-mean)*rstd + beta (transpose back)
    final_kernel<<<dim3(HW / 32, CIN / 32, BATCH), 256>>>(x, gamma, beta, out);
}